// round 9
// baseline (speedup 1.0000x reference)
#include <cuda_runtime.h>
#include <math.h>
#include <stdint.h>

typedef unsigned int u32;
typedef unsigned long long u64;

#define NN 2000
#define BB 64
#define TT 12
#define DD 16
#define HH 64

constexpr int CIN0 = 65;
constexpr int CIN1 = 128;
constexpr int F0   = BB * CIN0;   // 4160
constexpr int F1   = BB * CIN1;   // 8192
constexpr int KC0  = 3 * CIN0;    // 195
constexpr int KC1  = 3 * CIN1;    // 384
constexpr int KP   = 2048;        // padded node dim (k)
constexpr int NBMAX = 8192;

// ---------------- fp32 scratch ----------------
__device__ float g_A[NN * NN];
__device__ float g_gW0[NN * KC0 * 2 * HH];
__device__ float g_uW0[NN * KC0 * HH];
__device__ float g_gW1[NN * KC1 * 2 * HH];
__device__ float g_uW1[NN * KC1 * HH];
__device__ float g_gb0[NN * 2 * HH];
__device__ float g_ub0[NN * HH];
__device__ float g_gb1[NN * 2 * HH];
__device__ float g_ub1[NN * HH];
__device__ float g_xc[NN * F1];
__device__ float g_y1[NN * F1];
__device__ float g_y2[NN * F1];
__device__ float g_zr[NN * 2 * HH * BB];
__device__ float g_h0[NN * HH * BB];
__device__ float g_h1[NN * HH * BB];

// ---------------- int8 slice operands ----------------
// A slices row-major [m][k]; X slices transposed [col][k]. 4 digits of 7 bits.
__device__ char g_qA[4][(size_t)KP * KP];
__device__ char g_qX[4][(size_t)NBMAX * KP];
__device__ float g_sA[KP];       // power-of-two row scales of A
__device__ float g_sAinv[KP];
__device__ float g_sX[NBMAX];    // power-of-two column scales of X
__device__ float g_sXinv[NBMAX];

// pass tables: digit pairs (s,t) with s+t<=3, smallest weight first
__constant__ int c_SAq[10] = {3, 0, 2, 1, 2, 0, 1, 1, 0, 0};
__constant__ int c_SBq[10] = {0, 3, 1, 2, 0, 2, 1, 0, 1, 0};
__constant__ float c_Wq[10] = {
    1.1641532182693481e-10f, 1.1641532182693481e-10f,   // 2^-33
    1.1641532182693481e-10f, 1.1641532182693481e-10f,
    1.4901161193847656e-08f, 1.4901161193847656e-08f,   // 2^-26
    1.4901161193847656e-08f,
    1.9073486328125e-06f, 1.9073486328125e-06f,          // 2^-19
    2.44140625e-04f };                                   // 2^-12

// ---------------- PTX helpers ----------------
#define CP_ASYNC16(d, s) asm volatile("cp.async.cg.shared.global [%0], [%1], 16;" :: "r"((u32)(d)), "l"(s) : "memory")
#define CP_COMMIT()  asm volatile("cp.async.commit_group;" ::: "memory")
#define CP_WAIT2()   asm volatile("cp.async.wait_group 2;" ::: "memory")

__device__ __forceinline__ u32 smem_to_u32(const void* p) {
    u32 a;
    asm("{ .reg .u64 t; cvta.to.shared.u64 t, %1; cvt.u32.u64 %0, t; }" : "=r"(a) : "l"(p));
    return a;
}
__device__ __forceinline__ void ldsm4(u32& r0, u32& r1, u32& r2, u32& r3, u32 addr) {
    asm volatile("ldmatrix.sync.aligned.m8n8.x4.shared.b16 {%0,%1,%2,%3}, [%4];"
                 : "=r"(r0), "=r"(r1), "=r"(r2), "=r"(r3) : "r"(addr));
}
__device__ __forceinline__ void mma_s8(int* d, const u32* a, const u32* b) {
    asm volatile("mma.sync.aligned.m16n8k32.row.col.s32.s8.s8.s32 "
                 "{%0,%1,%2,%3}, {%4,%5,%6,%7}, {%8,%9}, {%0,%1,%2,%3};"
                 : "+r"(d[0]), "+r"(d[1]), "+r"(d[2]), "+r"(d[3])
                 : "r"(a[0]), "r"(a[1]), "r"(a[2]), "r"(a[3]), "r"(b[0]), "r"(b[1]));
}

// exact 4-digit quantization: v = s * (q0*2^-6 + q1*2^-13 + q2*2^-20 + q3*2^-27) + eps,
// |eps| <= s*2^-28.  inv must be an exact power of two with |v*inv| <= 1.
__device__ __forceinline__ void quant4(float v, float inv, int& q0, int& q1, int& q2, int& q3) {
    float u = v * inv;                 // exact
    float f0 = rintf(u * 64.f);
    float r  = fmaf(u, 64.f, -f0);     // exact residual, |r| <= 0.5
    float f1 = rintf(r * 128.f);
    r = fmaf(r, 128.f, -f1);
    float f2 = rintf(r * 128.f);
    r = fmaf(r, 128.f, -f2);
    float f3 = rintf(r * 128.f);
    q0 = (int)f0; q1 = (int)f1; q2 = (int)f2; q3 = (int)f3;
}

// ---------------- adjacency softmax (+ row scale) ----------------
__global__ void __launch_bounds__(256) adj_softmax_kernel(const float* __restrict__ E) {
    __shared__ float row[NN];
    __shared__ float sred[8];
    int n = blockIdx.x, tid = threadIdx.x;
    int lane = tid & 31, wid = tid >> 5;
    float en[DD];
#pragma unroll
    for (int d = 0; d < DD; d++) en[d] = E[n * DD + d];
    float lmax = 0.f;
    for (int m = tid; m < NN; m += 256) {
        const float* em = &E[m * DD];
        float s = 0.f;
#pragma unroll
        for (int d = 0; d < DD; d++) s += en[d] * em[d];
        s = fmaxf(s, 0.f);
        row[m] = s;
        lmax = fmaxf(lmax, s);
    }
#pragma unroll
    for (int o = 16; o; o >>= 1) lmax = fmaxf(lmax, __shfl_xor_sync(0xffffffffu, lmax, o));
    if (lane == 0) sred[wid] = lmax;
    __syncthreads();
    float bmax = sred[0];
#pragma unroll
    for (int w = 1; w < 8; w++) bmax = fmaxf(bmax, sred[w]);
    float lsum = 0.f;
    for (int m = tid; m < NN; m += 256) {
        float e = expf(row[m] - bmax);
        row[m] = e;
        lsum += e;
    }
#pragma unroll
    for (int o = 16; o; o >>= 1) lsum += __shfl_xor_sync(0xffffffffu, lsum, o);
    __syncthreads();
    if (lane == 0) sred[wid] = lsum;
    __syncthreads();
    float bsum = 0.f;
#pragma unroll
    for (int w = 0; w < 8; w++) bsum += sred[w];
    float inv = 1.f / bsum;
    for (int m = tid; m < NN; m += 256) g_A[(size_t)n * NN + m] = row[m] * inv;
    if (tid == 0) {
        // row max of softmax output = inv (max exp = 1). Power-of-two ceiling.
        int e; frexpf(inv, &e);
        g_sA[n] = ldexpf(1.f, e);
        g_sAinv[n] = ldexpf(1.f, -e);
    }
}

// ---------------- quantize A (once) ----------------
__global__ void __launch_bounds__(256) quantA_kernel() {
    size_t idx = (size_t)blockIdx.x * 256 + threadIdx.x;
    if (idx >= (size_t)KP * KP) return;
    int row = (int)(idx >> 11), col = (int)(idx & 2047);
    float v = 0.f, inv = 0.f;
    if (row < NN && col < NN) { v = g_A[(size_t)row * NN + col]; inv = g_sAinv[row]; }
    int q0, q1, q2, q3;
    quant4(v, inv, q0, q1, q2, q3);
    g_qA[0][idx] = (char)q0; g_qA[1][idx] = (char)q1;
    g_qA[2][idx] = (char)q2; g_qA[3][idx] = (char)q3;
}

// ---------------- column max (power-of-two scale) for X ----------------
__global__ void __launch_bounds__(256) colmax_kernel(const float* __restrict__ src, int ld, int c0, int NC) {
    __shared__ float red[8][32];
    int ci = threadIdx.x & 31, ms = threadIdx.x >> 5;
    int c = blockIdx.x * 32 + ci;
    float mx = 0.f;
    if (c < NC)
        for (int m = ms; m < NN; m += 8) mx = fmaxf(mx, fabsf(src[(size_t)m * ld + c0 + c]));
    red[ms][ci] = mx;
    __syncthreads();
    if (ms == 0 && c < NC) {
#pragma unroll
        for (int s = 1; s < 8; s++) mx = fmaxf(mx, red[s][ci]);
        int e = 0;
        if (mx > 0.f) frexpf(mx, &e);
        g_sX[c] = ldexpf(1.f, e);
        g_sXinv[c] = ldexpf(1.f, -e);
    }
}

// ---------------- transpose + quantize X ----------------
__global__ void __launch_bounds__(256) quantT_kernel(const float* __restrict__ src, int ld, int c0, int NC) {
    __shared__ float tile[32][33];
    int cx0 = blockIdx.x * 32, m0 = blockIdx.y * 32;
    int lx = threadIdx.x & 31, ly = threadIdx.x >> 5;
#pragma unroll
    for (int rr = 0; rr < 4; rr++) {
        int m = m0 + ly + rr * 8, c = cx0 + lx;
        float v = 0.f;
        if (m < NN && c < NC) v = src[(size_t)m * ld + c0 + c];
        tile[ly + rr * 8][lx] = v;
    }
    __syncthreads();
#pragma unroll
    for (int rr = 0; rr < 4; rr++) {
        int c = cx0 + ly + rr * 8;
        int m = m0 + lx;
        if (c < NC) {
            float v = tile[lx][ly + rr * 8];
            float inv = g_sXinv[c];
            int q0, q1, q2, q3;
            quant4(v, inv, q0, q1, q2, q3);
            size_t o = (size_t)c * KP + m;
            g_qX[0][o] = (char)q0; g_qX[1][o] = (char)q1;
            g_qX[2][o] = (char)q2; g_qX[3][o] = (char)q3;
        }
    }
}

// ---------------- int8 Ozaki GEMM: C = alpha*sA*sX*(sum of exact digit products) + beta*Cs ----
// 128x128 C-tile, 256 threads, warp grid 2(m) x 4(n), warp tile 64x32.
// chunk = 64 k (s8 bytes); per chunk 2 x k32 mma. 10 passes x 32 chunks = 320 chunks.
// s32 accumulation is exact; drained exactly to fp32 after each pass.
constexpr int SMEM_MM = 4 * 20480;   // 4 stages x (A 128x80B + B 128x80B)
__global__ void __launch_bounds__(256, 1) gemm_mma_kernel(
    const float* __restrict__ Cs, float* __restrict__ C,
    int Ncols, int ldc, float alpha, float beta)
{
    extern __shared__ char smem[];
    u32 sb = smem_to_u32(smem);
    int tid = threadIdx.x, wid = tid >> 5, lane = tid & 31;
    int bm = blockIdx.y * 128, bn = blockIdx.x * 128;
    int wm = (wid >> 2) * 64, wn = (wid & 3) * 32;
    const int NCH = 320;

    int   acc[4][4][4];
    float sum[4][4][4];
#pragma unroll
    for (int i = 0; i < 4; i++)
#pragma unroll
        for (int j = 0; j < 4; j++)
#pragma unroll
            for (int k = 0; k < 4; k++) { acc[i][j][k] = 0; sum[i][j][k] = 0.f; }

    int lrow = tid >> 1;             // 0..127
    int lseg = (tid & 1) * 2;        // 0 or 2

    auto stage = [&](int c) {
        if (c < NCH) {
            int q = c >> 5;
            int k0 = (c & 31) * 64;
            const char* Ap = g_qA[c_SAq[q]] + (size_t)(bm + lrow) * KP + k0;
            const char* Bp = g_qX[c_SBq[q]] + (size_t)(bn + lrow) * KP + k0;
            u32 base = sb + (c & 3) * 20480 + lrow * 80;
#pragma unroll
            for (int s = 0; s < 2; s++) {
                CP_ASYNC16(base + (lseg + s) * 16, Ap + (lseg + s) * 16);
                CP_ASYNC16(base + 10240 + (lseg + s) * 16, Bp + (lseg + s) * 16);
            }
        }
        CP_COMMIT();
    };

    stage(0); stage(1); stage(2);

    for (int c = 0; c < NCH; c++) {
        CP_WAIT2();
        __syncthreads();
        stage(c + 3);
        u32 aBase = sb + (c & 3) * 20480;
        u32 bBase = aBase + 10240;
#pragma unroll
        for (int kh = 0; kh < 2; kh++) {
            u32 a[4][4];
#pragma unroll
            for (int mf = 0; mf < 4; mf++) {
                int row = wm + mf * 16 + (lane & 7) + ((lane >> 3) & 1) * 8;
                ldsm4(a[mf][0], a[mf][1], a[mf][2], a[mf][3],
                      aBase + row * 80 + kh * 32 + (lane >> 4) * 16);
            }
            u32 b[4][2];
#pragma unroll
            for (int g = 0; g < 2; g++) {
                int col = wn + g * 16 + (lane & 7) + ((lane >> 3) & 1) * 8;
                u32 r0, r1, r2, r3;
                ldsm4(r0, r1, r2, r3, bBase + col * 80 + kh * 32 + (lane >> 4) * 16);
                b[g * 2][0] = r0;     b[g * 2][1] = r2;
                b[g * 2 + 1][0] = r1; b[g * 2 + 1][1] = r3;
            }
#pragma unroll
            for (int mf = 0; mf < 4; mf++)
#pragma unroll
                for (int nf = 0; nf < 4; nf++)
                    mma_s8(acc[mf][nf], a[mf], b[nf]);
        }
        if ((c & 31) == 31) {     // end of pass: exact drain (|acc| <= 2^23)
            float w = c_Wq[c >> 5];
#pragma unroll
            for (int i = 0; i < 4; i++)
#pragma unroll
                for (int j = 0; j < 4; j++)
#pragma unroll
                    for (int k = 0; k < 4; k++) {
                        sum[i][j][k] = fmaf((float)acc[i][j][k], w, sum[i][j][k]);
                        acc[i][j][k] = 0;
                    }
        }
    }

    // epilogue with scale recombination
#pragma unroll
    for (int mf = 0; mf < 4; mf++) {
#pragma unroll
        for (int nf = 0; nf < 4; nf++) {
            int r0 = bm + wm + mf * 16 + (lane >> 2);
            int cc = bn + wn + nf * 8 + (lane & 3) * 2;
            if (cc < Ncols) {
                bool ok1 = (cc + 1) < Ncols;
                float sx0 = g_sX[cc];
                float sx1 = ok1 ? g_sX[cc + 1] : 0.f;
#pragma unroll
                for (int hh2 = 0; hh2 < 2; hh2++) {
                    int row = r0 + hh2 * 8;
                    if (row < NN) {
                        float sa = g_sA[row] * alpha;
                        float v0 = sum[mf][nf][hh2 * 2 + 0] * sa * sx0;
                        float v1 = sum[mf][nf][hh2 * 2 + 1] * sa * sx1;
                        if (beta != 0.f) {
                            v0 += beta * Cs[(size_t)row * ldc + cc];
                            if (ok1) v1 += beta * Cs[(size_t)row * ldc + cc + 1];
                        }
                        C[(size_t)row * ldc + cc] = v0;
                        if (ok1) C[(size_t)row * ldc + cc + 1] = v1;
                    }
                }
            }
        }
    }
}

// ---------------- fp32 GEMM (weight folding only) ----------------
__global__ void __launch_bounds__(256) sgemm_kernel(
    const float* __restrict__ A, const float* __restrict__ B, float* __restrict__ C,
    int M, int Ncols, int K, int lda, int ldb, int ldc)
{
    constexpr int BM = 128, BN = 128, BK = 8;
    __shared__ float As[BK][BM];
    __shared__ float Bs[BK][BN];
    int tid = threadIdx.x;
    int bm = blockIdx.y * BM, bn = blockIdx.x * BN;
    int tx = tid & 15, ty = tid >> 4;
    float acc[8][8];
#pragma unroll
    for (int i = 0; i < 8; i++)
#pragma unroll
        for (int j = 0; j < 8; j++) acc[i][j] = 0.f;
    int arow = tid >> 1, acol = (tid & 1) * 4;
    int brow = tid >> 5, bcol = (tid & 31) * 4;
    bool aok = (bm + arow) < M;
    bool bok = (bn + bcol) < Ncols;
    for (int k0 = 0; k0 < K; k0 += BK) {
        float4 av = make_float4(0.f, 0.f, 0.f, 0.f);
        float4 bv = make_float4(0.f, 0.f, 0.f, 0.f);
        if (aok) av = *(const float4*)&A[(size_t)(bm + arow) * lda + k0 + acol];
        if (bok) bv = *(const float4*)&B[(size_t)(k0 + brow) * ldb + bn + bcol];
        As[acol + 0][arow] = av.x; As[acol + 1][arow] = av.y;
        As[acol + 2][arow] = av.z; As[acol + 3][arow] = av.w;
        *(float4*)&Bs[brow][bcol] = bv;
        __syncthreads();
#pragma unroll
        for (int kk = 0; kk < BK; kk++) {
            float a[8], b[8];
            *(float4*)&a[0] = *(const float4*)&As[kk][ty * 8];
            *(float4*)&a[4] = *(const float4*)&As[kk][ty * 8 + 4];
            *(float4*)&b[0] = *(const float4*)&Bs[kk][tx * 8];
            *(float4*)&b[4] = *(const float4*)&Bs[kk][tx * 8 + 4];
#pragma unroll
            for (int i = 0; i < 8; i++)
#pragma unroll
                for (int j = 0; j < 8; j++) acc[i][j] += a[i] * b[j];
        }
        __syncthreads();
    }
#pragma unroll
    for (int i = 0; i < 8; i++) {
        int row = bm + ty * 8 + i;
        if (row >= M) continue;
#pragma unroll
        for (int j = 0; j < 8; j++) {
            int col = bn + tx * 8 + j;
            if (col < Ncols) C[(size_t)row * ldc + col] = acc[i][j];
        }
    }
}

// ---------------- per-node batched GEMM + fused GRU epilogue ----------------
template <int CIN, int OUT, bool GATE>
__global__ void __launch_bounds__(256) node_gemm_kernel(
    const float* __restrict__ xg0, const float* __restrict__ xg1, const float* __restrict__ xg2,
    const float* __restrict__ W, const float* __restrict__ bias,
    float* __restrict__ zr, float* __restrict__ h)
{
    constexpr int KC = 3 * CIN;
    constexpr int F = CIN * BB;
    constexpr int OPT = OUT / 16;
    __shared__ float Xs[8][BB];
    __shared__ float Ws[8][OUT];
    int n = blockIdx.x;
    int tid = threadIdx.x;
    int tx = tid & 15, ty = tid >> 4;
    float acc[OPT][4];
#pragma unroll
    for (int oi = 0; oi < OPT; oi++)
#pragma unroll
        for (int bi = 0; bi < 4; bi++) acc[oi][bi] = 0.f;
    for (int rc = 0; rc < KC; rc += 8) {
#pragma unroll
        for (int e = tid; e < 8 * BB; e += 256) {
            int i = e >> 6, b = e & 63;
            int r = rc + i;
            float v = 0.f;
            if (r < KC) {
                int k = r / CIN;
                int c = r - k * CIN;
                const float* base = (k == 0) ? xg0 : ((k == 1) ? xg1 : xg2);
                v = base[(size_t)n * F + c * BB + b];
            }
            Xs[i][b] = v;
        }
#pragma unroll
        for (int e4 = tid; e4 < 8 * OUT / 4; e4 += 256) {
            int e = e4 * 4;
            int i = e / OUT, o = e % OUT;
            int r = rc + i;
            float4 v = make_float4(0.f, 0.f, 0.f, 0.f);
            if (r < KC) v = *(const float4*)&W[((size_t)n * KC + r) * OUT + o];
            *(float4*)&Ws[i][o] = v;
        }
        __syncthreads();
#pragma unroll
        for (int i = 0; i < 8; i++) {
            float bvals[4];
            *(float4*)&bvals[0] = *(const float4*)&Xs[i][tx * 4];
            float wv[OPT];
#pragma unroll
            for (int q = 0; q < OPT; q += 4)
                *(float4*)&wv[q] = *(const float4*)&Ws[i][ty * OPT + q];
#pragma unroll
            for (int oi = 0; oi < OPT; oi++)
#pragma unroll
                for (int bi = 0; bi < 4; bi++) acc[oi][bi] += wv[oi] * bvals[bi];
        }
        __syncthreads();
    }
#pragma unroll
    for (int oi = 0; oi < OPT; oi++) {
        int o = ty * OPT + oi;
        float bia = bias[(size_t)n * OUT + o];
#pragma unroll
        for (int bi = 0; bi < 4; bi++) {
            int b = tx * 4 + bi;
            float v = acc[oi][bi] + bia;
            if (GATE) {
                zr[((size_t)n * (2 * HH) + o) * BB + b] = 1.f / (1.f + expf(-v));
            } else {
                float hc = tanhf(v);
                float r = zr[((size_t)n * (2 * HH) + HH + o) * BB + b];
                size_t hi = ((size_t)n * HH + o) * BB + b;
                float hv = h[hi];
                h[hi] = r * hv + (1.f - r) * hc;
            }
        }
    }
}

// ---------------- prep kernels ----------------
__global__ void prep_xc0_kernel(const float* __restrict__ src, int t) {
    long idx = (long)blockIdx.x * blockDim.x + threadIdx.x;
    if (idx >= (long)NN * F0) return;
    int m = (int)(idx / F0);
    int col = (int)(idx - (long)m * F0);
    float v;
    if (col < BB) v = src[((size_t)(col * TT + t)) * NN + m];
    else          v = g_h0[(size_t)m * (HH * BB) + (col - BB)];
    g_xc[idx] = v;
}
__global__ void prep_xc0b_kernel() {
    long idx = (long)blockIdx.x * blockDim.x + threadIdx.x;
    if (idx >= (long)NN * HH * BB) return;
    int m = (int)(idx >> 12);
    int e = (int)(idx & 4095);
    g_xc[(size_t)m * F0 + BB + e] = g_zr[(size_t)m * (2 * HH * BB) + e] * g_h0[idx];
}
__global__ void prep_xc1_kernel() {
    long idx = (long)blockIdx.x * blockDim.x + threadIdx.x;
    if (idx >= (long)NN * F1) return;
    int m = (int)(idx >> 13);
    int e = (int)(idx & 8191);
    float v = (e < HH * BB) ? g_h0[(size_t)m * (HH * BB) + e]
                            : g_h1[(size_t)m * (HH * BB) + (e - HH * BB)];
    g_xc[idx] = v;
}
__global__ void prep_xc1b_kernel() {
    long idx = (long)blockIdx.x * blockDim.x + threadIdx.x;
    if (idx >= (long)NN * HH * BB) return;
    int m = (int)(idx >> 12);
    int e = (int)(idx & 4095);
    g_xc[(size_t)m * F1 + HH * BB + e] = g_zr[(size_t)m * (2 * HH * BB) + e] * g_h1[idx];
}

// ---------------- final projection ----------------
__global__ void __launch_bounds__(256) final_kernel(
    const float* __restrict__ cw, const float* __restrict__ cb, float* __restrict__ out)
{
    __shared__ float hs[HH * BB];
    __shared__ float cws[TT * HH];
    __shared__ float cbs[TT];
    int n = blockIdx.x, tid = threadIdx.x;
    for (int e = tid; e < HH * BB; e += 256) hs[e] = g_h1[(size_t)n * HH * BB + e];
    for (int e = tid; e < TT * HH; e += 256) cws[e] = cw[e];
    if (tid < TT) cbs[tid] = cb[tid];
    __syncthreads();
    for (int p = tid; p < BB * TT; p += 256) {
        int b = p / TT, o = p - b * TT;
        float s = cbs[o];
#pragma unroll
        for (int k = 0; k < HH; k++) s += hs[k * BB + b] * cws[o * HH + k];
        out[((size_t)(b * TT + o)) * NN + n] = s;
    }
}

// ---------------- host ----------------
static void sgemm(const float* A, const float* B, float* C, int M, int Nc, int K,
                  int lda, int ldb, int ldc)
{
    dim3 g((Nc + 127) / 128, (M + 127) / 128);
    sgemm_kernel<<<g, 256>>>(A, B, C, M, Nc, K, lda, ldb, ldc);
}

static void gemm_pair(float* xc_, float* y1_, float* y2_, int c0, int NC, int ld)
{
    dim3 gt((NC + 31) / 32, 64);
    dim3 gg((NC + 127) / 128, 16);
    int gcm = (NC + 31) / 32;
    colmax_kernel<<<gcm, 256>>>(xc_, ld, c0, NC);
    quantT_kernel<<<gt, 256>>>(xc_, ld, c0, NC);
    gemm_mma_kernel<<<gg, 256, SMEM_MM>>>(nullptr, y1_ + c0, NC, ld, 1.f, 0.f);
    colmax_kernel<<<gcm, 256>>>(y1_, ld, c0, NC);
    quantT_kernel<<<gt, 256>>>(y1_, ld, c0, NC);
    gemm_mma_kernel<<<gg, 256, SMEM_MM>>>(xc_ + c0, y2_ + c0, NC, ld, 2.f, -1.f);
}

extern "C" void kernel_launch(void* const* d_in, const int* in_sizes, int n_in,
                              void* d_out, int out_size)
{
    const float* src  = (const float*)d_in[0];
    const float* E    = (const float*)d_in[1];
    const float* gwp0 = (const float*)d_in[2];
    const float* gbp0 = (const float*)d_in[3];
    const float* uwp0 = (const float*)d_in[4];
    const float* ubp0 = (const float*)d_in[5];
    const float* gwp1 = (const float*)d_in[6];
    const float* gbp1 = (const float*)d_in[7];
    const float* uwp1 = (const float*)d_in[8];
    const float* ubp1 = (const float*)d_in[9];
    const float* cw   = (const float*)d_in[10];
    const float* cb   = (const float*)d_in[11];
    float* out = (float*)d_out;

    cudaFuncSetAttribute(gemm_mma_kernel, cudaFuncAttributeMaxDynamicSharedMemorySize, SMEM_MM);

    float *gW0_, *uW0_, *gW1_, *uW1_, *gb0_, *ub0_, *gb1_, *ub1_;
    float *xc_, *y1_, *y2_, *zr_, *h0_, *h1_;
    cudaGetSymbolAddress((void**)&gW0_, g_gW0);
    cudaGetSymbolAddress((void**)&uW0_, g_uW0);
    cudaGetSymbolAddress((void**)&gW1_, g_gW1);
    cudaGetSymbolAddress((void**)&uW1_, g_uW1);
    cudaGetSymbolAddress((void**)&gb0_, g_gb0);
    cudaGetSymbolAddress((void**)&ub0_, g_ub0);
    cudaGetSymbolAddress((void**)&gb1_, g_gb1);
    cudaGetSymbolAddress((void**)&ub1_, g_ub1);
    cudaGetSymbolAddress((void**)&xc_,  g_xc);
    cudaGetSymbolAddress((void**)&y1_,  g_y1);
    cudaGetSymbolAddress((void**)&y2_,  g_y2);
    cudaGetSymbolAddress((void**)&zr_,  g_zr);
    cudaGetSymbolAddress((void**)&h0_,  g_h0);
    cudaGetSymbolAddress((void**)&h1_,  g_h1);

    cudaMemsetAsync(h0_, 0, (size_t)NN * HH * BB * sizeof(float), 0);
    cudaMemsetAsync(h1_, 0, (size_t)NN * HH * BB * sizeof(float), 0);

    adj_softmax_kernel<<<NN, 256>>>(E);
    quantA_kernel<<<(int)(((size_t)KP * KP + 255) / 256), 256>>>();

    sgemm(E, gwp0, gW0_, NN, KC0 * 2 * HH, DD, DD, KC0 * 2 * HH, KC0 * 2 * HH);
    sgemm(E, uwp0, uW0_, NN, KC0 * HH,     DD, DD, KC0 * HH,     KC0 * HH);
    sgemm(E, gwp1, gW1_, NN, KC1 * 2 * HH, DD, DD, KC1 * 2 * HH, KC1 * 2 * HH);
    sgemm(E, uwp1, uW1_, NN, KC1 * HH,     DD, DD, KC1 * HH,     KC1 * HH);
    sgemm(E, gbp0, gb0_, NN, 2 * HH, DD, DD, 2 * HH, 2 * HH);
    sgemm(E, ubp0, ub0_, NN, HH,     DD, DD, HH,     HH);
    sgemm(E, gbp1, gb1_, NN, 2 * HH, DD, DD, 2 * HH, 2 * HH);
    sgemm(E, ubp1, ub1_, NN, HH,     DD, DD, HH,     HH);

    const int PB = 256;
    for (int t = 0; t < TT; t++) {
        prep_xc0_kernel<<<(int)(((long)NN * F0 + PB - 1) / PB), PB>>>(src, t);
        gemm_pair(xc_, y1_, y2_, 0, F0, F0);
        node_gemm_kernel<CIN0, 2 * HH, true><<<NN, 256>>>(xc_, y1_, y2_, gW0_, gb0_, zr_, h0_);
        prep_xc0b_kernel<<<(int)(((long)NN * HH * BB + PB - 1) / PB), PB>>>();
        gemm_pair(xc_, y1_, y2_, BB, F0 - BB, F0);
        node_gemm_kernel<CIN0, HH, false><<<NN, 256>>>(xc_, y1_, y2_, uW0_, ub0_, zr_, h0_);

        prep_xc1_kernel<<<(int)(((long)NN * F1 + PB - 1) / PB), PB>>>();
        gemm_pair(xc_, y1_, y2_, 0, F1, F1);
        node_gemm_kernel<CIN1, 2 * HH, true><<<NN, 256>>>(xc_, y1_, y2_, gW1_, gb1_, zr_, h1_);
        prep_xc1b_kernel<<<(int)(((long)NN * HH * BB + PB - 1) / PB), PB>>>();
        gemm_pair(xc_, y1_, y2_, HH * BB, F1 - HH * BB, F1);
        node_gemm_kernel<CIN1, HH, false><<<NN, 256>>>(xc_, y1_, y2_, uW1_, ub1_, zr_, h1_);
    }

    final_kernel<<<NN, 256>>>(cw, cb, out);
}

// round 10
// speedup vs baseline: 2.4182x; 2.4182x over previous
#include <cuda_runtime.h>
#include <math.h>
#include <stdint.h>

typedef unsigned int u32;
typedef unsigned long long u64;

#define NN 2000
#define BB 64
#define TT 12
#define DD 16
#define HH 64

constexpr int CIN0 = 65;
constexpr int CIN1 = 128;
constexpr int F0   = BB * CIN0;   // 4160
constexpr int F1   = BB * CIN1;   // 8192
constexpr int KC0  = 3 * CIN0;    // 195
constexpr int KC1  = 3 * CIN1;    // 384

// ---------------- device scratch ----------------
// stacked operator: rows 0..1999 = A, rows 2000..2047 = zero pad,
// rows 2048..4047 = 2A^2 - I, rows 4048..4095 unused (guarded)
__device__ float g_As[(size_t)4096 * NN];
__device__ float g_gW0[NN * KC0 * 2 * HH];
__device__ float g_uW0[NN * KC0 * HH];
__device__ float g_gW1[NN * KC1 * 2 * HH];
__device__ float g_uW1[NN * KC1 * HH];
__device__ float g_gb0[NN * 2 * HH];
__device__ float g_ub0[NN * HH];
__device__ float g_gb1[NN * 2 * HH];
__device__ float g_ub1[NN * HH];
__device__ float g_xc[NN * F1];
__device__ float g_y1[NN * F1];
__device__ float g_y2[NN * F1];
__device__ float g_zr[NN * 2 * HH * BB];
__device__ float g_h0[NN * HH * BB];
__device__ float g_h1[NN * HH * BB];

// ---------------- helpers ----------------
__device__ __forceinline__ u64 pack2(float x, float y) {
    u64 r; asm("mov.b64 %0, {%1,%2};" : "=l"(r) : "f"(x), "f"(y)); return r;
}
__device__ __forceinline__ void unpack2(u64 v, float& x, float& y) {
    asm("mov.b64 {%0,%1}, %2;" : "=f"(x), "=f"(y) : "l"(v));
}
__device__ __forceinline__ void ffma2(u64& d, u64 a, u64 b) {
    asm("fma.rn.f32x2 %0, %1, %2, %0;" : "+l"(d) : "l"(a), "l"(b));
}
__device__ __forceinline__ u32 smem_to_u32(const void* p) {
    u32 a;
    asm("{ .reg .u64 t; cvta.to.shared.u64 t, %1; cvt.u32.u64 %0, t; }" : "=r"(a) : "l"(p));
    return a;
}
#define CP_ASYNC16(d, s) asm volatile("cp.async.cg.shared.global [%0], [%1], 16;" :: "r"((u32)(d)), "l"(s) : "memory")
#define CP_COMMIT()  asm volatile("cp.async.commit_group;" ::: "memory")
#define CP_WAIT0()   asm volatile("cp.async.wait_group 0;" ::: "memory")

// ---------------- adjacency softmax (writes rows 0..1999 of g_As) ----------------
__global__ void __launch_bounds__(256) adj_softmax_kernel(const float* __restrict__ E) {
    __shared__ float row[NN];
    __shared__ float sred[8];
    int n = blockIdx.x, tid = threadIdx.x;
    int lane = tid & 31, wid = tid >> 5;
    float en[DD];
#pragma unroll
    for (int d = 0; d < DD; d++) en[d] = E[n * DD + d];
    float lmax = 0.f;
    for (int m = tid; m < NN; m += 256) {
        const float* em = &E[m * DD];
        float s = 0.f;
#pragma unroll
        for (int d = 0; d < DD; d++) s += en[d] * em[d];
        s = fmaxf(s, 0.f);
        row[m] = s;
        lmax = fmaxf(lmax, s);
    }
#pragma unroll
    for (int o = 16; o; o >>= 1) lmax = fmaxf(lmax, __shfl_xor_sync(0xffffffffu, lmax, o));
    if (lane == 0) sred[wid] = lmax;
    __syncthreads();
    float bmax = sred[0];
#pragma unroll
    for (int w = 1; w < 8; w++) bmax = fmaxf(bmax, sred[w]);
    float lsum = 0.f;
    for (int m = tid; m < NN; m += 256) {
        float e = expf(row[m] - bmax);
        row[m] = e;
        lsum += e;
    }
#pragma unroll
    for (int o = 16; o; o >>= 1) lsum += __shfl_xor_sync(0xffffffffu, lsum, o);
    __syncthreads();
    if (lane == 0) sred[wid] = lsum;
    __syncthreads();
    float bsum = 0.f;
#pragma unroll
    for (int w = 0; w < 8; w++) bsum += sred[w];
    float inv = 1.f / bsum;
    for (int m = tid; m < NN; m += 256) g_As[(size_t)n * NN + m] = row[m] * inv;
}

__global__ void diag_fix_kernel() {
    int i = blockIdx.x * 256 + threadIdx.x;
    if (i < NN) g_As[(size_t)(2048 + i) * NN + i] -= 1.f;
}

// ---------------- main FFMA2 GEMM ----------------
// C = alpha * A(M x K) @ B(K x Ncols).  Output row r: r<m1 -> C1[r], else if
// r>=split && r-split<m2 -> C2[r-split], else discarded.  K % 16 == 0, Ncols % 4 == 0.
// 128x128 tile, 128 threads, 8(M) x 16(N) per thread, packed f32x2 accumulators.
constexpr int GK = 16;
__global__ void __launch_bounds__(128, 2) gemm_main_kernel(
    const float* __restrict__ A, int MA,
    const float* __restrict__ B,
    float* __restrict__ C1, int m1,
    float* __restrict__ C2, int split, int m2,
    int Ncols, int K, int ldb, int ldc, float alpha)
{
    __shared__ float As[2][GK][128];
    __shared__ float Bs[2][GK][128];
    int tid = threadIdx.x;
    int tx = tid & 7, ty = tid >> 3;
    int bm = blockIdx.y * 128, bn = blockIdx.x * 128;
    int arow = bm + tid;
    bool aok = arow < MA;
    const float* Ap = A + (size_t)arow * K;
    u32 sBs = smem_to_u32(&Bs[0][0][0]);

    u64 acc2[8][8];
#pragma unroll
    for (int i = 0; i < 8; i++)
#pragma unroll
        for (int p = 0; p < 8; p++) acc2[i][p] = 0ULL;

    int nk = K / GK;

    auto stageB = [&](int kt, int buf) {
#pragma unroll
        for (int i = 0; i < 4; i++) {
            int e = tid + 128 * i;
            int k = e >> 5, c4 = e & 31;
            int col = bn + c4 * 4;
            if (col < Ncols) {
                CP_ASYNC16(sBs + buf * (GK * 128 * 4) + k * 512 + c4 * 16,
                           B + (size_t)(kt * GK + k) * ldb + col);
            } else {
                *(float4*)&Bs[buf][k][c4 * 4] = make_float4(0.f, 0.f, 0.f, 0.f);
            }
        }
        CP_COMMIT();
    };
    auto loadA = [&](int kt, float4* av) {
#pragma unroll
        for (int j = 0; j < 4; j++)
            av[j] = aok ? *(const float4*)(Ap + kt * GK + j * 4)
                        : make_float4(0.f, 0.f, 0.f, 0.f);
    };
    auto stsA = [&](int buf, const float4* av) {
#pragma unroll
        for (int j = 0; j < 4; j++) {
            As[buf][j * 4 + 0][tid] = av[j].x;
            As[buf][j * 4 + 1][tid] = av[j].y;
            As[buf][j * 4 + 2][tid] = av[j].z;
            As[buf][j * 4 + 3][tid] = av[j].w;
        }
    };

    float4 av[4];
    stageB(0, 0);
    loadA(0, av);
    stsA(0, av);
    CP_WAIT0();
    __syncthreads();

    for (int kt = 0; kt < nk; kt++) {
        int buf = kt & 1;
        bool more = (kt + 1) < nk;
        if (more) { stageB(kt + 1, buf ^ 1); loadA(kt + 1, av); }
#pragma unroll 4
        for (int kk = 0; kk < GK; kk++) {
            const float* as = &As[buf][kk][ty * 8];
            float4 a0 = *(const float4*)as;
            float4 a1 = *(const float4*)(as + 4);
            const ulonglong2* bsrc = (const ulonglong2*)&Bs[buf][kk][tx * 16];
            ulonglong2 q0 = bsrc[0], q1 = bsrc[1], q2 = bsrc[2], q3 = bsrc[3];
            u64 bp[8] = { q0.x, q0.y, q1.x, q1.y, q2.x, q2.y, q3.x, q3.y };
            float a[8] = { a0.x, a0.y, a0.z, a0.w, a1.x, a1.y, a1.z, a1.w };
#pragma unroll
            for (int i = 0; i < 8; i++) {
                u64 ad = pack2(a[i], a[i]);
#pragma unroll
                for (int p = 0; p < 8; p++) ffma2(acc2[i][p], ad, bp[p]);
            }
        }
        if (more) stsA(buf ^ 1, av);
        CP_WAIT0();
        __syncthreads();
    }

#pragma unroll
    for (int i = 0; i < 8; i++) {
        int row = bm + ty * 8 + i;
        float* dst;
        if (row < m1) dst = C1 + (size_t)row * ldc;
        else if (row >= split && (row - split) < m2) dst = C2 + (size_t)(row - split) * ldc;
        else continue;
#pragma unroll
        for (int p = 0; p < 8; p++) {
            int cc = bn + tx * 16 + 2 * p;
            if (cc < Ncols) {
                float v0, v1;
                unpack2(acc2[i][p], v0, v1);
                dst[cc]     = alpha * v0;
                dst[cc + 1] = alpha * v1;
            }
        }
    }
}

// ---------------- fp32 GEMM (weight folding only, K=16) ----------------
__global__ void __launch_bounds__(256) sgemm_kernel(
    const float* __restrict__ A, const float* __restrict__ B, float* __restrict__ C,
    int M, int Ncols, int K, int lda, int ldb, int ldc)
{
    constexpr int BM = 128, BN = 128, BK = 8;
    __shared__ float As[BK][BM];
    __shared__ float Bs[BK][BN];
    int tid = threadIdx.x;
    int bm = blockIdx.y * BM, bn = blockIdx.x * BN;
    int tx = tid & 15, ty = tid >> 4;
    float acc[8][8];
#pragma unroll
    for (int i = 0; i < 8; i++)
#pragma unroll
        for (int j = 0; j < 8; j++) acc[i][j] = 0.f;
    int arow = tid >> 1, acol = (tid & 1) * 4;
    int brow = tid >> 5, bcol = (tid & 31) * 4;
    bool aok = (bm + arow) < M;
    bool bok = (bn + bcol) < Ncols;
    for (int k0 = 0; k0 < K; k0 += BK) {
        float4 av = make_float4(0.f, 0.f, 0.f, 0.f);
        float4 bv = make_float4(0.f, 0.f, 0.f, 0.f);
        if (aok) av = *(const float4*)&A[(size_t)(bm + arow) * lda + k0 + acol];
        if (bok) bv = *(const float4*)&B[(size_t)(k0 + brow) * ldb + bn + bcol];
        As[acol + 0][arow] = av.x; As[acol + 1][arow] = av.y;
        As[acol + 2][arow] = av.z; As[acol + 3][arow] = av.w;
        *(float4*)&Bs[brow][bcol] = bv;
        __syncthreads();
#pragma unroll
        for (int kk = 0; kk < BK; kk++) {
            float a[8], b[8];
            *(float4*)&a[0] = *(const float4*)&As[kk][ty * 8];
            *(float4*)&a[4] = *(const float4*)&As[kk][ty * 8 + 4];
            *(float4*)&b[0] = *(const float4*)&Bs[kk][tx * 8];
            *(float4*)&b[4] = *(const float4*)&Bs[kk][tx * 8 + 4];
#pragma unroll
            for (int i = 0; i < 8; i++)
#pragma unroll
                for (int j = 0; j < 8; j++) acc[i][j] += a[i] * b[j];
        }
        __syncthreads();
    }
#pragma unroll
    for (int i = 0; i < 8; i++) {
        int row = bm + ty * 8 + i;
        if (row >= M) continue;
#pragma unroll
        for (int j = 0; j < 8; j++) {
            int col = bn + tx * 8 + j;
            if (col < Ncols) C[(size_t)row * ldc + col] = acc[i][j];
        }
    }
}

// ---------------- per-node batched GEMM + fused GRU epilogue ----------------
template <int CIN, int OUT, bool GATE>
__global__ void __launch_bounds__(256) node_gemm_kernel(
    const float* __restrict__ xg0, const float* __restrict__ xg1, const float* __restrict__ xg2,
    const float* __restrict__ W, const float* __restrict__ bias,
    float* __restrict__ zr, float* __restrict__ h)
{
    constexpr int KC = 3 * CIN;
    constexpr int F = CIN * BB;
    constexpr int OPT = OUT / 16;
    __shared__ float Xs[8][BB];
    __shared__ float Ws[8][OUT];
    int n = blockIdx.x;
    int tid = threadIdx.x;
    int tx = tid & 15, ty = tid >> 4;
    float acc[OPT][4];
#pragma unroll
    for (int oi = 0; oi < OPT; oi++)
#pragma unroll
        for (int bi = 0; bi < 4; bi++) acc[oi][bi] = 0.f;
    for (int rc = 0; rc < KC; rc += 8) {
#pragma unroll
        for (int e = tid; e < 8 * BB; e += 256) {
            int i = e >> 6, b = e & 63;
            int r = rc + i;
            float v = 0.f;
            if (r < KC) {
                int k = r / CIN;
                int c = r - k * CIN;
                const float* base = (k == 0) ? xg0 : ((k == 1) ? xg1 : xg2);
                v = base[(size_t)n * F + c * BB + b];
            }
            Xs[i][b] = v;
        }
#pragma unroll
        for (int e4 = tid; e4 < 8 * OUT / 4; e4 += 256) {
            int e = e4 * 4;
            int i = e / OUT, o = e % OUT;
            int r = rc + i;
            float4 v = make_float4(0.f, 0.f, 0.f, 0.f);
            if (r < KC) v = *(const float4*)&W[((size_t)n * KC + r) * OUT + o];
            *(float4*)&Ws[i][o] = v;
        }
        __syncthreads();
#pragma unroll
        for (int i = 0; i < 8; i++) {
            float bvals[4];
            *(float4*)&bvals[0] = *(const float4*)&Xs[i][tx * 4];
            float wv[OPT];
#pragma unroll
            for (int q = 0; q < OPT; q += 4)
                *(float4*)&wv[q] = *(const float4*)&Ws[i][ty * OPT + q];
#pragma unroll
            for (int oi = 0; oi < OPT; oi++)
#pragma unroll
                for (int bi = 0; bi < 4; bi++) acc[oi][bi] += wv[oi] * bvals[bi];
        }
        __syncthreads();
    }
#pragma unroll
    for (int oi = 0; oi < OPT; oi++) {
        int o = ty * OPT + oi;
        float bia = bias[(size_t)n * OUT + o];
#pragma unroll
        for (int bi = 0; bi < 4; bi++) {
            int b = tx * 4 + bi;
            float v = acc[oi][bi] + bia;
            if (GATE) {
                zr[((size_t)n * (2 * HH) + o) * BB + b] = 1.f / (1.f + expf(-v));
            } else {
                float hc = tanhf(v);
                float r = zr[((size_t)n * (2 * HH) + HH + o) * BB + b];
                size_t hi = ((size_t)n * HH + o) * BB + b;
                float hv = h[hi];
                h[hi] = r * hv + (1.f - r) * hc;
            }
        }
    }
}

// ---------------- prep kernels ----------------
__global__ void prep_xc0_kernel(const float* __restrict__ src, int t) {
    long idx = (long)blockIdx.x * blockDim.x + threadIdx.x;
    if (idx >= (long)NN * F0) return;
    int m = (int)(idx / F0);
    int col = (int)(idx - (long)m * F0);
    float v;
    if (col < BB) v = src[((size_t)(col * TT + t)) * NN + m];
    else          v = g_h0[(size_t)m * (HH * BB) + (col - BB)];
    g_xc[idx] = v;
}
__global__ void prep_xc0b_kernel() {
    long idx = (long)blockIdx.x * blockDim.x + threadIdx.x;
    if (idx >= (long)NN * HH * BB) return;
    int m = (int)(idx >> 12);
    int e = (int)(idx & 4095);
    g_xc[(size_t)m * F0 + BB + e] = g_zr[(size_t)m * (2 * HH * BB) + e] * g_h0[idx];
}
__global__ void prep_xc1_kernel() {
    long idx = (long)blockIdx.x * blockDim.x + threadIdx.x;
    if (idx >= (long)NN * F1) return;
    int m = (int)(idx >> 13);
    int e = (int)(idx & 8191);
    float v = (e < HH * BB) ? g_h0[(size_t)m * (HH * BB) + e]
                            : g_h1[(size_t)m * (HH * BB) + (e - HH * BB)];
    g_xc[idx] = v;
}
__global__ void prep_xc1b_kernel() {
    long idx = (long)blockIdx.x * blockDim.x + threadIdx.x;
    if (idx >= (long)NN * HH * BB) return;
    int m = (int)(idx >> 12);
    int e = (int)(idx & 4095);
    g_xc[(size_t)m * F1 + HH * BB + e] = g_zr[(size_t)m * (2 * HH * BB) + e] * g_h1[idx];
}

// ---------------- final projection ----------------
__global__ void __launch_bounds__(256) final_kernel(
    const float* __restrict__ cw, const float* __restrict__ cb, float* __restrict__ out)
{
    __shared__ float hs[HH * BB];
    __shared__ float cws[TT * HH];
    __shared__ float cbs[TT];
    int n = blockIdx.x, tid = threadIdx.x;
    for (int e = tid; e < HH * BB; e += 256) hs[e] = g_h1[(size_t)n * HH * BB + e];
    for (int e = tid; e < TT * HH; e += 256) cws[e] = cw[e];
    if (tid < TT) cbs[tid] = cb[tid];
    __syncthreads();
    for (int p = tid; p < BB * TT; p += 256) {
        int b = p / TT, o = p - b * TT;
        float s = cbs[o];
#pragma unroll
        for (int k = 0; k < HH; k++) s += hs[k * BB + b] * cws[o * HH + k];
        out[((size_t)(b * TT + o)) * NN + n] = s;
    }
}

// ---------------- host ----------------
static void sgemm(const float* A, const float* B, float* C, int M, int Nc, int K,
                  int lda, int ldb, int ldc)
{
    dim3 g((Nc + 127) / 128, (M + 127) / 128);
    sgemm_kernel<<<g, 256>>>(A, B, C, M, Nc, K, lda, ldb, ldc);
}

static void gemm_pair(const float* As_, float* xcp, float* y1p, float* y2p,
                      int c0, int NC, int ld)
{
    dim3 gg((NC + 127) / 128, 32);
    gemm_main_kernel<<<gg, 128>>>(As_, 4048, xcp + c0,
                                  y1p + c0, NN, y2p + c0, 2048, NN,
                                  NC, NN, ld, ld, 1.f);
}

extern "C" void kernel_launch(void* const* d_in, const int* in_sizes, int n_in,
                              void* d_out, int out_size)
{
    const float* src  = (const float*)d_in[0];
    const float* E    = (const float*)d_in[1];
    const float* gwp0 = (const float*)d_in[2];
    const float* gbp0 = (const float*)d_in[3];
    const float* uwp0 = (const float*)d_in[4];
    const float* ubp0 = (const float*)d_in[5];
    const float* gwp1 = (const float*)d_in[6];
    const float* gbp1 = (const float*)d_in[7];
    const float* uwp1 = (const float*)d_in[8];
    const float* ubp1 = (const float*)d_in[9];
    const float* cw   = (const float*)d_in[10];
    const float* cb   = (const float*)d_in[11];
    float* out = (float*)d_out;

    float *As_, *gW0_, *uW0_, *gW1_, *uW1_, *gb0_, *ub0_, *gb1_, *ub1_;
    float *xc_, *y1_, *y2_, *zr_, *h0_, *h1_;
    cudaGetSymbolAddress((void**)&As_,  g_As);
    cudaGetSymbolAddress((void**)&gW0_, g_gW0);
    cudaGetSymbolAddress((void**)&uW0_, g_uW0);
    cudaGetSymbolAddress((void**)&gW1_, g_gW1);
    cudaGetSymbolAddress((void**)&uW1_, g_uW1);
    cudaGetSymbolAddress((void**)&gb0_, g_gb0);
    cudaGetSymbolAddress((void**)&ub0_, g_ub0);
    cudaGetSymbolAddress((void**)&gb1_, g_gb1);
    cudaGetSymbolAddress((void**)&ub1_, g_ub1);
    cudaGetSymbolAddress((void**)&xc_,  g_xc);
    cudaGetSymbolAddress((void**)&y1_,  g_y1);
    cudaGetSymbolAddress((void**)&y2_,  g_y2);
    cudaGetSymbolAddress((void**)&zr_,  g_zr);
    cudaGetSymbolAddress((void**)&h0_,  g_h0);
    cudaGetSymbolAddress((void**)&h1_,  g_h1);

    cudaMemsetAsync(h0_, 0, (size_t)NN * HH * BB * sizeof(float), 0);
    cudaMemsetAsync(h1_, 0, (size_t)NN * HH * BB * sizeof(float), 0);
    // zero pad rows 2000..2047 of the stacked operator
    cudaMemsetAsync(As_ + (size_t)2000 * NN, 0, (size_t)48 * NN * sizeof(float), 0);

    adj_softmax_kernel<<<NN, 256>>>(E);

    // A2 = 2*A@A (rows 2048..4047), then subtract I on the diagonal
    {
        dim3 gg((NN + 127) / 128, 16);
        gemm_main_kernel<<<gg, 128>>>(As_, NN, As_,
                                      As_ + (size_t)2048 * NN, NN,
                                      nullptr, 1 << 30, 0,
                                      NN, NN, NN, NN, 2.f);
        diag_fix_kernel<<<(NN + 255) / 256, 256>>>();
    }

    sgemm(E, gwp0, gW0_, NN, KC0 * 2 * HH, DD, DD, KC0 * 2 * HH, KC0 * 2 * HH);
    sgemm(E, uwp0, uW0_, NN, KC0 * HH,     DD, DD, KC0 * HH,     KC0 * HH);
    sgemm(E, gwp1, gW1_, NN, KC1 * 2 * HH, DD, DD, KC1 * 2 * HH, KC1 * 2 * HH);
    sgemm(E, uwp1, uW1_, NN, KC1 * HH,     DD, DD, KC1 * HH,     KC1 * HH);
    sgemm(E, gbp0, gb0_, NN, 2 * HH, DD, DD, 2 * HH, 2 * HH);
    sgemm(E, ubp0, ub0_, NN, HH,     DD, DD, HH,     HH);
    sgemm(E, gbp1, gb1_, NN, 2 * HH, DD, DD, 2 * HH, 2 * HH);
    sgemm(E, ubp1, ub1_, NN, HH,     DD, DD, HH,     HH);

    const int PB = 256;
    for (int t = 0; t < TT; t++) {
        prep_xc0_kernel<<<(int)(((long)NN * F0 + PB - 1) / PB), PB>>>(src, t);
        gemm_pair(As_, xc_, y1_, y2_, 0, F0, F0);
        node_gemm_kernel<CIN0, 2 * HH, true><<<NN, 256>>>(xc_, y1_, y2_, gW0_, gb0_, zr_, h0_);
        prep_xc0b_kernel<<<(int)(((long)NN * HH * BB + PB - 1) / PB), PB>>>();
        gemm_pair(As_, xc_, y1_, y2_, BB, F0 - BB, F0);
        node_gemm_kernel<CIN0, HH, false><<<NN, 256>>>(xc_, y1_, y2_, uW0_, ub0_, zr_, h0_);

        prep_xc1_kernel<<<(int)(((long)NN * F1 + PB - 1) / PB), PB>>>();
        gemm_pair(As_, xc_, y1_, y2_, 0, F1, F1);
        node_gemm_kernel<CIN1, 2 * HH, true><<<NN, 256>>>(xc_, y1_, y2_, gW1_, gb1_, zr_, h1_);
        prep_xc1b_kernel<<<(int)(((long)NN * HH * BB + PB - 1) / PB), PB>>>();
        gemm_pair(As_, xc_, y1_, y2_, HH * BB, F1 - HH * BB, F1);
        node_gemm_kernel<CIN1, HH, false><<<NN, 256>>>(xc_, y1_, y2_, uW1_, ub1_, zr_, h1_);
    }

    final_kernel<<<NN, 256>>>(cw, cb, out);
}

// round 12
// speedup vs baseline: 3.9368x; 1.6280x over previous
#include <cuda_runtime.h>
#include <math.h>
#include <stdint.h>

typedef unsigned int u32;
typedef unsigned long long u64;

#define NN 2000
#define BB 64
#define TT 12
#define DD 16
#define HH 64

constexpr int CIN0 = 65;
constexpr int CIN1 = 128;
constexpr int F0   = BB * CIN0;   // 4160
constexpr int F1   = BB * CIN1;   // 8192
constexpr int KC0  = 3 * CIN0;    // 195
constexpr int KC1  = 3 * CIN1;    // 384
constexpr int LDA_T = 4096;       // AsT row length (m-padded)

// ---------------- device scratch ----------------
// stacked operator rows: 0..1999 = A, 2000..2047 = 0, 2048..4047 = 2A^2 - I
__device__ float g_As[(size_t)4096 * NN];
__device__ float g_AsT[(size_t)2048 * LDA_T];   // AsT[k][m] = As[m][k]
__device__ float g_gW0[NN * KC0 * 2 * HH];
__device__ float g_uW0[NN * KC0 * HH];
__device__ float g_gW1[NN * KC1 * 2 * HH];
__device__ float g_uW1[NN * KC1 * HH];
__device__ float g_gb0[NN * 2 * HH];
__device__ float g_ub0[NN * HH];
__device__ float g_gb1[NN * 2 * HH];
__device__ float g_ub1[NN * HH];
__device__ float g_xc[NN * F1];
__device__ float g_y1[NN * F1];
__device__ float g_y2[NN * F1];
__device__ float g_zr[NN * 2 * HH * BB];
__device__ float g_h0[NN * HH * BB];
__device__ float g_h1[NN * HH * BB];

// ---------------- helpers ----------------
__device__ __forceinline__ u64 pack2(float x, float y) {
    u64 r; asm("mov.b64 %0, {%1,%2};" : "=l"(r) : "f"(x), "f"(y)); return r;
}
__device__ __forceinline__ void unpack2(u64 v, float& x, float& y) {
    asm("mov.b64 {%0,%1}, %2;" : "=f"(x), "=f"(y) : "l"(v));
}
__device__ __forceinline__ void ffma2(u64& d, u64 a, u64 b) {
    asm("fma.rn.f32x2 %0, %1, %2, %0;" : "+l"(d) : "l"(a), "l"(b));
}
__device__ __forceinline__ u32 smem_to_u32(const void* p) {
    u32 a;
    asm("{ .reg .u64 t; cvta.to.shared.u64 t, %1; cvt.u32.u64 %0, t; }" : "=r"(a) : "l"(p));
    return a;
}
#define CP_ASYNC16(d, s) asm volatile("cp.async.cg.shared.global [%0], [%1], 16;" :: "r"((u32)(d)), "l"(s) : "memory")
#define CP_COMMIT()  asm volatile("cp.async.commit_group;" ::: "memory")
#define CP_WAIT2()   asm volatile("cp.async.wait_group 2;" ::: "memory")

// ---------------- adjacency softmax (rows 0..1999 of g_As) ----------------
__global__ void __launch_bounds__(256) adj_softmax_kernel(const float* __restrict__ E) {
    __shared__ float row[NN];
    __shared__ float sred[8];
    int n = blockIdx.x, tid = threadIdx.x;
    int lane = tid & 31, wid = tid >> 5;
    float en[DD];
#pragma unroll
    for (int d = 0; d < DD; d++) en[d] = E[n * DD + d];
    float lmax = 0.f;
    for (int m = tid; m < NN; m += 256) {
        const float* em = &E[m * DD];
        float s = 0.f;
#pragma unroll
        for (int d = 0; d < DD; d++) s += en[d] * em[d];
        s = fmaxf(s, 0.f);
        row[m] = s;
        lmax = fmaxf(lmax, s);
    }
#pragma unroll
    for (int o = 16; o; o >>= 1) lmax = fmaxf(lmax, __shfl_xor_sync(0xffffffffu, lmax, o));
    if (lane == 0) sred[wid] = lmax;
    __syncthreads();
    float bmax = sred[0];
#pragma unroll
    for (int w = 1; w < 8; w++) bmax = fmaxf(bmax, sred[w]);
    float lsum = 0.f;
    for (int m = tid; m < NN; m += 256) {
        float e = expf(row[m] - bmax);
        row[m] = e;
        lsum += e;
    }
#pragma unroll
    for (int o = 16; o; o >>= 1) lsum += __shfl_xor_sync(0xffffffffu, lsum, o);
    __syncthreads();
    if (lane == 0) sred[wid] = lsum;
    __syncthreads();
    float bsum = 0.f;
#pragma unroll
    for (int w = 0; w < 8; w++) bsum += sred[w];
    float inv = 1.f / bsum;
    for (int m = tid; m < NN; m += 256) g_As[(size_t)n * NN + m] = row[m] * inv;
}

__global__ void diag_fix_kernel() {
    int i = blockIdx.x * 256 + threadIdx.x;
    if (i < NN) g_As[(size_t)(2048 + i) * NN + i] -= 1.f;
}

// ---------------- transpose As[m][k] -> AsT[k][m] for m in [mbase, mbase+2048) ----------------
__global__ void __launch_bounds__(256) transposeA_kernel(int mbase) {
    __shared__ float t[32][33];
    int k0 = blockIdx.x * 32, m0 = mbase + blockIdx.y * 32;
    int lx = threadIdx.x & 31, ly = threadIdx.x >> 5;
#pragma unroll
    for (int rr = 0; rr < 4; rr++) {
        int m = m0 + ly + rr * 8, k = k0 + lx;
        float v = 0.f;
        if (m < 4048 && k < NN) v = g_As[(size_t)m * NN + k];
        t[ly + rr * 8][lx] = v;
    }
    __syncthreads();
#pragma unroll
    for (int rr = 0; rr < 4; rr++) {
        int k = k0 + ly + rr * 8;
        int m = m0 + lx;
        g_AsT[(size_t)k * LDA_T + m] = t[lx][ly + rr * 8];
    }
}

// ---------------- main FFMA2 GEMM: C = alpha * As(stacked) @ B ----------------
// A read from g_AsT (k-major). Output row r: r<m1 -> C1[r]; r>=split && r-split<m2 -> C2[r-split].
// K = NN (2000), BK = 16, 125 k-tiles. 128x128 C-tile, 256 threads, 8x8 thread tile,
// packed f32x2 accumulators, 4-stage cp.async ring, one barrier per tile.
constexpr int GBK = 16;
constexpr int STAGE_F = GBK * 128 * 2;            // floats per stage (A + B)
constexpr int SMEM_MAIN = 4 * STAGE_F * 4;        // 64 KB
__global__ void __launch_bounds__(256, 2) gemm_main_kernel(
    const float* __restrict__ B,
    float* __restrict__ C1, int m1,
    float* __restrict__ C2, int split, int m2,
    int Ncols, int ldb, int ldc, float alpha)
{
    extern __shared__ float smemf[];
    u32 sb = smem_to_u32(smemf);
    int tid = threadIdx.x;
    int tx = tid & 15, ty = tid >> 4;
    int bm = blockIdx.y * 128, bn = blockIdx.x * 128;
    const int nk = NN / GBK;   // 125

    u64 acc2[8][4];
#pragma unroll
    for (int i = 0; i < 8; i++)
#pragma unroll
        for (int p = 0; p < 4; p++) acc2[i][p] = 0ULL;

    auto stage = [&](int c) {
        if (c < nk) {
            int buf = c & 3;
            const float* At = g_AsT + (size_t)(c * GBK) * LDA_T + bm;
            const float* Bt = B + (size_t)(c * GBK) * ldb + bn;
#pragma unroll
            for (int i = 0; i < 2; i++) {
                int e = tid + i * 256;
                int k = e >> 5, c4 = e & 31;
                CP_ASYNC16(sb + buf * 16384 + k * 512 + c4 * 16,
                           At + (size_t)k * LDA_T + c4 * 4);
                if (bn + c4 * 4 < Ncols) {
                    CP_ASYNC16(sb + buf * 16384 + 8192 + k * 512 + c4 * 16,
                               Bt + (size_t)k * ldb + c4 * 4);
                } else {
                    *(float4*)(smemf + buf * STAGE_F + GBK * 128 + k * 128 + c4 * 4) =
                        make_float4(0.f, 0.f, 0.f, 0.f);
                }
            }
        }
        CP_COMMIT();
    };

    stage(0); stage(1); stage(2);

    for (int kt = 0; kt < nk; kt++) {
        int buf = kt & 3;
        CP_WAIT2();
        __syncthreads();
        stage(kt + 3);
#pragma unroll 4
        for (int kk = 0; kk < GBK; kk++) {
            const float* ap = smemf + buf * STAGE_F + kk * 128 + ty * 8;
            float4 a0 = *(const float4*)ap;
            float4 a1 = *(const float4*)(ap + 4);
            const u64* bp = (const u64*)(smemf + buf * STAGE_F + GBK * 128 + kk * 128 + tx * 8);
            u64 b0 = bp[0], b1 = bp[1], b2 = bp[2], b3 = bp[3];
            float a[8] = { a0.x, a0.y, a0.z, a0.w, a1.x, a1.y, a1.z, a1.w };
#pragma unroll
            for (int i = 0; i < 8; i++) {
                u64 ad = pack2(a[i], a[i]);
                ffma2(acc2[i][0], ad, b0);
                ffma2(acc2[i][1], ad, b1);
                ffma2(acc2[i][2], ad, b2);
                ffma2(acc2[i][3], ad, b3);
            }
        }
    }

#pragma unroll
    for (int i = 0; i < 8; i++) {
        int row = bm + ty * 8 + i;
        float* dst;
        if (row < m1) dst = C1 + (size_t)row * ldc;
        else if (row >= split && (row - split) < m2) dst = C2 + (size_t)(row - split) * ldc;
        else continue;
#pragma unroll
        for (int p = 0; p < 4; p++) {
            int cc = bn + tx * 8 + 2 * p;
            if (cc < Ncols) {
                float v0, v1;
                unpack2(acc2[i][p], v0, v1);
                dst[cc]     = alpha * v0;
                dst[cc + 1] = alpha * v1;
            }
        }
    }
}

// ---------------- fp32 GEMM (weight folding only, K=16) ----------------
__global__ void __launch_bounds__(256) sgemm_kernel(
    const float* __restrict__ A, const float* __restrict__ B, float* __restrict__ C,
    int M, int Ncols, int K, int lda, int ldb, int ldc)
{
    constexpr int BM = 128, BN = 128, BK = 8;
    __shared__ float As[BK][BM];
    __shared__ float Bs[BK][BN];
    int tid = threadIdx.x;
    int bm = blockIdx.y * BM, bn = blockIdx.x * BN;
    int tx = tid & 15, ty = tid >> 4;
    float acc[8][8];
#pragma unroll
    for (int i = 0; i < 8; i++)
#pragma unroll
        for (int j = 0; j < 8; j++) acc[i][j] = 0.f;
    int arow = tid >> 1, acol = (tid & 1) * 4;
    int brow = tid >> 5, bcol = (tid & 31) * 4;
    bool aok = (bm + arow) < M;
    bool bok = (bn + bcol) < Ncols;
    for (int k0 = 0; k0 < K; k0 += BK) {
        float4 av = make_float4(0.f, 0.f, 0.f, 0.f);
        float4 bv = make_float4(0.f, 0.f, 0.f, 0.f);
        if (aok) av = *(const float4*)&A[(size_t)(bm + arow) * lda + k0 + acol];
        if (bok) bv = *(const float4*)&B[(size_t)(k0 + brow) * ldb + bn + bcol];
        As[acol + 0][arow] = av.x; As[acol + 1][arow] = av.y;
        As[acol + 2][arow] = av.z; As[acol + 3][arow] = av.w;
        *(float4*)&Bs[brow][bcol] = bv;
        __syncthreads();
#pragma unroll
        for (int kk = 0; kk < BK; kk++) {
            float a[8], b[8];
            *(float4*)&a[0] = *(const float4*)&As[kk][ty * 8];
            *(float4*)&a[4] = *(const float4*)&As[kk][ty * 8 + 4];
            *(float4*)&b[0] = *(const float4*)&Bs[kk][tx * 8];
            *(float4*)&b[4] = *(const float4*)&Bs[kk][tx * 8 + 4];
#pragma unroll
            for (int i = 0; i < 8; i++)
#pragma unroll
                for (int j = 0; j < 8; j++) acc[i][j] += a[i] * b[j];
        }
        __syncthreads();
    }
#pragma unroll
    for (int i = 0; i < 8; i++) {
        int row = bm + ty * 8 + i;
        if (row >= M) continue;
#pragma unroll
        for (int j = 0; j < 8; j++) {
            int col = bn + tx * 8 + j;
            if (col < Ncols) C[(size_t)row * ldc + col] = acc[i][j];
        }
    }
}

// ---------------- per-node batched GEMM + fused GRU epilogue ----------------
template <int CIN, int OUT, bool GATE>
__global__ void __launch_bounds__(256) node_gemm_kernel(
    const float* __restrict__ xg0, const float* __restrict__ xg1, const float* __restrict__ xg2,
    const float* __restrict__ W, const float* __restrict__ bias,
    float* __restrict__ zr, float* __restrict__ h)
{
    constexpr int KC = 3 * CIN;
    constexpr int F = CIN * BB;
    constexpr int OPT = OUT / 16;
    __shared__ float Xs[8][BB];
    __shared__ float Ws[8][OUT];
    int n = blockIdx.x;
    int tid = threadIdx.x;
    int tx = tid & 15, ty = tid >> 4;
    float acc[OPT][4];
#pragma unroll
    for (int oi = 0; oi < OPT; oi++)
#pragma unroll
        for (int bi = 0; bi < 4; bi++) acc[oi][bi] = 0.f;
    for (int rc = 0; rc < KC; rc += 8) {
#pragma unroll
        for (int e = tid; e < 8 * BB; e += 256) {
            int i = e >> 6, b = e & 63;
            int r = rc + i;
            float v = 0.f;
            if (r < KC) {
                int k = r / CIN;
                int c = r - k * CIN;
                const float* base = (k == 0) ? xg0 : ((k == 1) ? xg1 : xg2);
                v = base[(size_t)n * F + c * BB + b];
            }
            Xs[i][b] = v;
        }
#pragma unroll
        for (int e4 = tid; e4 < 8 * OUT / 4; e4 += 256) {
            int e = e4 * 4;
            int i = e / OUT, o = e % OUT;
            int r = rc + i;
            float4 v = make_float4(0.f, 0.f, 0.f, 0.f);
            if (r < KC) v = *(const float4*)&W[((size_t)n * KC + r) * OUT + o];
            *(float4*)&Ws[i][o] = v;
        }
        __syncthreads();
#pragma unroll
        for (int i = 0; i < 8; i++) {
            float bvals[4];
            *(float4*)&bvals[0] = *(const float4*)&Xs[i][tx * 4];
            float wv[OPT];
#pragma unroll
            for (int q = 0; q < OPT; q += 4)
                *(float4*)&wv[q] = *(const float4*)&Ws[i][ty * OPT + q];
#pragma unroll
            for (int oi = 0; oi < OPT; oi++)
#pragma unroll
                for (int bi = 0; bi < 4; bi++) acc[oi][bi] += wv[oi] * bvals[bi];
        }
        __syncthreads();
    }
#pragma unroll
    for (int oi = 0; oi < OPT; oi++) {
        int o = ty * OPT + oi;
        float bia = bias[(size_t)n * OUT + o];
#pragma unroll
        for (int bi = 0; bi < 4; bi++) {
            int b = tx * 4 + bi;
            float v = acc[oi][bi] + bia;
            if (GATE) {
                zr[((size_t)n * (2 * HH) + o) * BB + b] = 1.f / (1.f + expf(-v));
            } else {
                float hc = tanhf(v);
                float r = zr[((size_t)n * (2 * HH) + HH + o) * BB + b];
                size_t hi = ((size_t)n * HH + o) * BB + b;
                float hv = h[hi];
                h[hi] = r * hv + (1.f - r) * hc;
            }
        }
    }
}

// ---------------- prep kernels ----------------
__global__ void prep_xc0_kernel(const float* __restrict__ src, int t) {
    long idx = (long)blockIdx.x * blockDim.x + threadIdx.x;
    if (idx >= (long)NN * F0) return;
    int m = (int)(idx / F0);
    int col = (int)(idx - (long)m * F0);
    float v;
    if (col < BB) v = src[((size_t)(col * TT + t)) * NN + m];
    else          v = g_h0[(size_t)m * (HH * BB) + (col - BB)];
    g_xc[idx] = v;
}
__global__ void prep_xc0b_kernel() {
    long idx = (long)blockIdx.x * blockDim.x + threadIdx.x;
    if (idx >= (long)NN * HH * BB) return;
    int m = (int)(idx >> 12);
    int e = (int)(idx & 4095);
    g_xc[(size_t)m * F0 + BB + e] = g_zr[(size_t)m * (2 * HH * BB) + e] * g_h0[idx];
}
__global__ void prep_xc1_kernel() {
    long idx = (long)blockIdx.x * blockDim.x + threadIdx.x;
    if (idx >= (long)NN * F1) return;
    int m = (int)(idx >> 13);
    int e = (int)(idx & 8191);
    float v = (e < HH * BB) ? g_h0[(size_t)m * (HH * BB) + e]
                            : g_h1[(size_t)m * (HH * BB) + (e - HH * BB)];
    g_xc[idx] = v;
}
__global__ void prep_xc1b_kernel() {
    long idx = (long)blockIdx.x * blockDim.x + threadIdx.x;
    if (idx >= (long)NN * HH * BB) return;
    int m = (int)(idx >> 12);
    int e = (int)(idx & 4095);
    g_xc[(size_t)m * F1 + HH * BB + e] = g_zr[(size_t)m * (2 * HH * BB) + e] * g_h1[idx];
}

// ---------------- final projection ----------------
__global__ void __launch_bounds__(256) final_kernel(
    const float* __restrict__ cw, const float* __restrict__ cb, float* __restrict__ out)
{
    __shared__ float hs[HH * BB];
    __shared__ float cws[TT * HH];
    __shared__ float cbs[TT];
    int n = blockIdx.x, tid = threadIdx.x;
    for (int e = tid; e < HH * BB; e += 256) hs[e] = g_h1[(size_t)n * HH * BB + e];
    for (int e = tid; e < TT * HH; e += 256) cws[e] = cw[e];
    if (tid < TT) cbs[tid] = cb[tid];
    __syncthreads();
    for (int p = tid; p < BB * TT; p += 256) {
        int b = p / TT, o = p - b * TT;
        float s = cbs[o];
#pragma unroll
        for (int k = 0; k < HH; k++) s += hs[k * BB + b] * cws[o * HH + k];
        out[((size_t)(b * TT + o)) * NN + n] = s;
    }
}

// ---------------- host ----------------
static void sgemm(const float* A, const float* B, float* C, int M, int Nc, int K,
                  int lda, int ldb, int ldc)
{
    dim3 g((Nc + 127) / 128, (M + 127) / 128);
    sgemm_kernel<<<g, 256>>>(A, B, C, M, Nc, K, lda, ldb, ldc);
}

static void gemm_pair(float* xcp, float* y1p, float* y2p, int c0, int NC, int ld)
{
    dim3 gg((NC + 127) / 128, 32);
    gemm_main_kernel<<<gg, 256, SMEM_MAIN>>>(xcp + c0,
                                             y1p + c0, NN, y2p + c0, 2048, NN,
                                             NC, ld, ld, 1.f);
}

extern "C" void kernel_launch(void* const* d_in, const int* in_sizes, int n_in,
                              void* d_out, int out_size)
{
    const float* src  = (const float*)d_in[0];
    const float* E    = (const float*)d_in[1];
    const float* gwp0 = (const float*)d_in[2];
    const float* gbp0 = (const float*)d_in[3];
    const float* uwp0 = (const float*)d_in[4];
    const float* ubp0 = (const float*)d_in[5];
    const float* gwp1 = (const float*)d_in[6];
    const float* gbp1 = (const float*)d_in[7];
    const float* uwp1 = (const float*)d_in[8];
    const float* ubp1 = (const float*)d_in[9];
    const float* cw   = (const float*)d_in[10];
    const float* cb   = (const float*)d_in[11];
    float* out = (float*)d_out;

    cudaFuncSetAttribute(gemm_main_kernel, cudaFuncAttributeMaxDynamicSharedMemorySize, SMEM_MAIN);

    float *As_, *gW0_, *uW0_, *gW1_, *uW1_, *gb0_, *ub0_, *gb1_, *ub1_;
    float *xc_, *y1_, *y2_, *zr_, *h0_, *h1_;
    cudaGetSymbolAddress((void**)&As_,  g_As);
    cudaGetSymbolAddress((void**)&gW0_, g_gW0);
    cudaGetSymbolAddress((void**)&uW0_, g_uW0);
    cudaGetSymbolAddress((void**)&gW1_, g_gW1);
    cudaGetSymbolAddress((void**)&uW1_, g_uW1);
    cudaGetSymbolAddress((void**)&gb0_, g_gb0);
    cudaGetSymbolAddress((void**)&ub0_, g_ub0);
    cudaGetSymbolAddress((void**)&gb1_, g_gb1);
    cudaGetSymbolAddress((void**)&ub1_, g_ub1);
    cudaGetSymbolAddress((void**)&xc_,  g_xc);
    cudaGetSymbolAddress((void**)&y1_,  g_y1);
    cudaGetSymbolAddress((void**)&y2_,  g_y2);
    cudaGetSymbolAddress((void**)&zr_,  g_zr);
    cudaGetSymbolAddress((void**)&h0_,  g_h0);
    cudaGetSymbolAddress((void**)&h1_,  g_h1);

    cudaMemsetAsync(h0_, 0, (size_t)NN * HH * BB * sizeof(float), 0);
    cudaMemsetAsync(h1_, 0, (size_t)NN * HH * BB * sizeof(float), 0);
    cudaMemsetAsync(As_ + (size_t)2000 * NN, 0, (size_t)48 * NN * sizeof(float), 0);

    adj_softmax_kernel<<<NN, 256>>>(E);

    // Build AsT for m in [0,2048) (A block), compute 2A^2 - I, then AsT for m in [2048,4096).
    {
        dim3 gt(64, 64);
        transposeA_kernel<<<gt, 256>>>(0);
        dim3 gg((NN + 127) / 128, 16);
        gemm_main_kernel<<<gg, 256, SMEM_MAIN>>>(As_,                     // B = A (row-major k x n)
                                                 As_ + (size_t)2048 * NN, // C1 -> As rows 2048..
                                                 NN, nullptr, 1 << 30, 0,
                                                 NN, NN, NN, 2.f);
        diag_fix_kernel<<<(NN + 255) / 256, 256>>>();
        transposeA_kernel<<<gt, 256>>>(2048);
    }

    sgemm(E, gwp0, gW0_, NN, KC0 * 2 * HH, DD, DD, KC0 * 2 * HH, KC0 * 2 * HH);
    sgemm(E, uwp0, uW0_, NN, KC0 * HH,     DD, DD, KC0 * HH,     KC0 * HH);
    sgemm(E, gwp1, gW1_, NN, KC1 * 2 * HH, DD, DD, KC1 * 2 * HH, KC1 * 2 * HH);
    sgemm(E, uwp1, uW1_, NN, KC1 * HH,     DD, DD, KC1 * HH,     KC1 * HH);
    sgemm(E, gbp0, gb0_, NN, 2 * HH, DD, DD, 2 * HH, 2 * HH);
    sgemm(E, ubp0, ub0_, NN, HH,     DD, DD, HH,     HH);
    sgemm(E, gbp1, gb1_, NN, 2 * HH, DD, DD, 2 * HH, 2 * HH);
    sgemm(E, ubp1, ub1_, NN, HH,     DD, DD, HH,     HH);

    const int PB = 256;
    for (int t = 0; t < TT; t++) {
        prep_xc0_kernel<<<(int)(((long)NN * F0 + PB - 1) / PB), PB>>>(src, t);
        gemm_pair(xc_, y1_, y2_, 0, F0, F0);
        node_gemm_kernel<CIN0, 2 * HH, true><<<NN, 256>>>(xc_, y1_, y2_, gW0_, gb0_, zr_, h0_);
        prep_xc0b_kernel<<<(int)(((long)NN * HH * BB + PB - 1) / PB), PB>>>();
        gemm_pair(xc_, y1_, y2_, BB, F0 - BB, F0);
        node_gemm_kernel<CIN0, HH, false><<<NN, 256>>>(xc_, y1_, y2_, uW0_, ub0_, zr_, h0_);

        prep_xc1_kernel<<<(int)(((long)NN * F1 + PB - 1) / PB), PB>>>();
        gemm_pair(xc_, y1_, y2_, 0, F1, F1);
        node_gemm_kernel<CIN1, 2 * HH, true><<<NN, 256>>>(xc_, y1_, y2_, gW1_, gb1_, zr_, h1_);
        prep_xc1b_kernel<<<(int)(((long)NN * HH * BB + PB - 1) / PB), PB>>>();
        gemm_pair(xc_, y1_, y2_, HH * BB, F1 - HH * BB, F1);
        node_gemm_kernel<CIN1, HH, false><<<NN, 256>>>(xc_, y1_, y2_, uW1_, ub1_, zr_, h1_);
    }

    final_kernel<<<NN, 256>>>(cw, cb, out);
}

// round 14
// speedup vs baseline: 4.1106x; 1.0441x over previous
#include <cuda_runtime.h>
#include <math.h>
#include <stdint.h>

typedef unsigned int u32;
typedef unsigned long long u64;

#define NN 2000
#define BB 64
#define TT 12
#define DD 16
#define HH 64

constexpr int CIN0 = 65;
constexpr int CIN1 = 128;
constexpr int F0   = BB * CIN0;   // 4160
constexpr int F1   = BB * CIN1;   // 8192
constexpr int KC0  = 3 * CIN0;    // 195
constexpr int KC1  = 3 * CIN1;    // 384
constexpr int LDA_T = 4096;       // AsT row length (m-padded)
constexpr int KPAD = 2048;        // padded k rows for B operands

// ---------------- device scratch ----------------
// stacked operator rows: 0..1999 = A, 2000..2047 = 0, 2048..4047 = 2A^2 - I
__device__ float g_As[(size_t)4096 * NN];
__device__ float g_AsT[(size_t)2048 * LDA_T];   // AsT[k][m] = As[m][k], zero for k>=2000 / m pad
__device__ float g_gW0[NN * KC0 * 2 * HH];
__device__ float g_uW0[NN * KC0 * HH];
__device__ float g_gW1[NN * KC1 * 2 * HH];
__device__ float g_uW1[NN * KC1 * HH];
__device__ float g_gb0[NN * 2 * HH];
__device__ float g_ub0[NN * HH];
__device__ float g_gb1[NN * 2 * HH];
__device__ float g_ub1[NN * HH];
__device__ float g_xc[(size_t)KPAD * F1];       // B operand: rows 2000..2047 zeroed
__device__ float g_y1[NN * F1];
__device__ float g_y2[NN * F1];
__device__ float g_zr[NN * 2 * HH * BB];
__device__ float g_h0[NN * HH * BB];
__device__ float g_h1[NN * HH * BB];

// ---------------- helpers ----------------
__device__ __forceinline__ u64 pack2(float x, float y) {
    u64 r; asm("mov.b64 %0, {%1,%2};" : "=l"(r) : "f"(x), "f"(y)); return r;
}
__device__ __forceinline__ void unpack2(u64 v, float& x, float& y) {
    asm("mov.b64 {%0,%1}, %2;" : "=f"(x), "=f"(y) : "l"(v));
}
__device__ __forceinline__ void ffma2(u64& d, u64 a, u64 b) {
    asm("fma.rn.f32x2 %0, %1, %2, %0;" : "+l"(d) : "l"(a), "l"(b));
}
__device__ __forceinline__ u32 smem_to_u32(const void* p) {
    u32 a;
    asm("{ .reg .u64 t; cvta.to.shared.u64 t, %1; cvt.u32.u64 %0, t; }" : "=r"(a) : "l"(p));
    return a;
}
#define CP_ASYNC16(d, s) asm volatile("cp.async.cg.shared.global [%0], [%1], 16;" :: "r"((u32)(d)), "l"(s) : "memory")
#define CP_COMMIT()  asm volatile("cp.async.commit_group;" ::: "memory")
#define CP_WAIT1()   asm volatile("cp.async.wait_group 1;" ::: "memory")

// ---------------- adjacency softmax (rows 0..1999 of g_As) ----------------
__global__ void __launch_bounds__(256) adj_softmax_kernel(const float* __restrict__ E) {
    __shared__ float row[NN];
    __shared__ float sred[8];
    int n = blockIdx.x, tid = threadIdx.x;
    int lane = tid & 31, wid = tid >> 5;
    float en[DD];
#pragma unroll
    for (int d = 0; d < DD; d++) en[d] = E[n * DD + d];
    float lmax = 0.f;
    for (int m = tid; m < NN; m += 256) {
        const float* em = &E[m * DD];
        float s = 0.f;
#pragma unroll
        for (int d = 0; d < DD; d++) s += en[d] * em[d];
        s = fmaxf(s, 0.f);
        row[m] = s;
        lmax = fmaxf(lmax, s);
    }
#pragma unroll
    for (int o = 16; o; o >>= 1) lmax = fmaxf(lmax, __shfl_xor_sync(0xffffffffu, lmax, o));
    if (lane == 0) sred[wid] = lmax;
    __syncthreads();
    float bmax = sred[0];
#pragma unroll
    for (int w = 1; w < 8; w++) bmax = fmaxf(bmax, sred[w]);
    float lsum = 0.f;
    for (int m = tid; m < NN; m += 256) {
        float e = expf(row[m] - bmax);
        row[m] = e;
        lsum += e;
    }
#pragma unroll
    for (int o = 16; o; o >>= 1) lsum += __shfl_xor_sync(0xffffffffu, lsum, o);
    __syncthreads();
    if (lane == 0) sred[wid] = lsum;
    __syncthreads();
    float bsum = 0.f;
#pragma unroll
    for (int w = 0; w < 8; w++) bsum += sred[w];
    float inv = 1.f / bsum;
    for (int m = tid; m < NN; m += 256) g_As[(size_t)n * NN + m] = row[m] * inv;
}

__global__ void diag_fix_kernel() {
    int i = blockIdx.x * 256 + threadIdx.x;
    if (i < NN) g_As[(size_t)(2048 + i) * NN + i] -= 1.f;
}

// ---------------- transpose As[m][k] -> AsT[k][m] for m in [mbase, mbase+2048) ----------------
__global__ void __launch_bounds__(256) transposeA_kernel(int mbase) {
    __shared__ float t[32][33];
    int k0 = blockIdx.x * 32, m0 = mbase + blockIdx.y * 32;
    int lx = threadIdx.x & 31, ly = threadIdx.x >> 5;
#pragma unroll
    for (int rr = 0; rr < 4; rr++) {
        int m = m0 + ly + rr * 8, k = k0 + lx;
        float v = 0.f;
        if (m < 4048 && k < NN) v = g_As[(size_t)m * NN + k];
        t[ly + rr * 8][lx] = v;
    }
    __syncthreads();
#pragma unroll
    for (int rr = 0; rr < 4; rr++) {
        int k = k0 + ly + rr * 8;
        int m = m0 + lx;
        g_AsT[(size_t)k * LDA_T + m] = t[lx][ly + rr * 8];
    }
}

// ---------------- main FFMA2 GEMM: C = alpha * As(stacked) @ B ----------------
// A from g_AsT (k-major, zero for k>=2000). B must be valid for k<2016 (pad rows zeroed).
// Output row r: r<m1 -> C1[r]; r>=split && r-split<m2 -> C2[r-split].
// 128x128 C-tile, 256 threads, 8x8 thread tile, packed f32x2 accumulators,
// BK=32, 3-stage cp.async ring, one barrier per tile. 63 tiles cover k<2016.
constexpr int GBK = 32;
constexpr int STAGE_F = GBK * 128 * 2;            // 8192 floats per stage (A + B)
constexpr int SMEM_MAIN = 3 * STAGE_F * 4;        // 96 KB
__global__ void __launch_bounds__(256, 2) gemm_main_kernel(
    const float* __restrict__ B,
    float* __restrict__ C1, int m1,
    float* __restrict__ C2, int split, int m2,
    int Ncols, int ldb, int ldc, float alpha)
{
    extern __shared__ float smemf[];
    u32 sb = smem_to_u32(smemf);
    int tid = threadIdx.x;
    int tx = tid & 15, ty = tid >> 4;
    int bm = blockIdx.y * 128, bn = blockIdx.x * 128;
    const int nk = 63;   // 63 * 32 = 2016 >= 2000

    u64 acc2[8][4];
#pragma unroll
    for (int i = 0; i < 8; i++)
#pragma unroll
        for (int p = 0; p < 4; p++) acc2[i][p] = 0ULL;

    auto stage = [&](int c) {
        if (c < nk) {
            int buf = c % 3;
            const float* At = g_AsT + (size_t)(c * GBK) * LDA_T + bm;
            const float* Bt = B + (size_t)(c * GBK) * ldb + bn;
#pragma unroll
            for (int i = 0; i < 4; i++) {
                int e = tid + i * 256;          // 0..1023
                int k = e >> 5, c4 = e & 31;
                CP_ASYNC16(sb + buf * 32768 + k * 512 + c4 * 16,
                           At + (size_t)k * LDA_T + c4 * 4);
                if (bn + c4 * 4 < Ncols) {
                    CP_ASYNC16(sb + buf * 32768 + 16384 + k * 512 + c4 * 16,
                               Bt + (size_t)k * ldb + c4 * 4);
                } else {
                    *(float4*)(smemf + buf * STAGE_F + GBK * 128 + k * 128 + c4 * 4) =
                        make_float4(0.f, 0.f, 0.f, 0.f);
                }
            }
        }
        CP_COMMIT();
    };

    stage(0); stage(1);

    for (int kt = 0; kt < nk; kt++) {
        int buf = kt % 3;
        CP_WAIT1();
        __syncthreads();
        stage(kt + 2);
#pragma unroll 4
        for (int kk = 0; kk < GBK; kk++) {
            const float* ap = smemf + buf * STAGE_F + kk * 128 + ty * 8;
            float4 a0 = *(const float4*)ap;
            float4 a1 = *(const float4*)(ap + 4);
            const u64* bp = (const u64*)(smemf + buf * STAGE_F + GBK * 128 + kk * 128 + tx * 8);
            u64 b0 = bp[0], b1 = bp[1], b2 = bp[2], b3 = bp[3];
            float a[8] = { a0.x, a0.y, a0.z, a0.w, a1.x, a1.y, a1.z, a1.w };
#pragma unroll
            for (int i = 0; i < 8; i++) {
                u64 ad = pack2(a[i], a[i]);
                ffma2(acc2[i][0], ad, b0);
                ffma2(acc2[i][1], ad, b1);
                ffma2(acc2[i][2], ad, b2);
                ffma2(acc2[i][3], ad, b3);
            }
        }
    }

#pragma unroll
    for (int i = 0; i < 8; i++) {
        int row = bm + ty * 8 + i;
        float* dst;
        if (row < m1) dst = C1 + (size_t)row * ldc;
        else if (row >= split && (row - split) < m2) dst = C2 + (size_t)(row - split) * ldc;
        else continue;
#pragma unroll
        for (int p = 0; p < 4; p++) {
            int cc = bn + tx * 8 + 2 * p;
            if (cc < Ncols) {
                float v0, v1;
                unpack2(acc2[i][p], v0, v1);
                dst[cc]     = alpha * v0;
                dst[cc + 1] = alpha * v1;
            }
        }
    }
}

// ---------------- fp32 GEMM (weight folding only, K=16) ----------------
__global__ void __launch_bounds__(256) sgemm_kernel(
    const float* __restrict__ A, const float* __restrict__ B, float* __restrict__ C,
    int M, int Ncols, int K, int lda, int ldb, int ldc)
{
    constexpr int BM = 128, BN = 128, BK = 8;
    __shared__ float As[BK][BM];
    __shared__ float Bs[BK][BN];
    int tid = threadIdx.x;
    int bm = blockIdx.y * BM, bn = blockIdx.x * BN;
    int tx = tid & 15, ty = tid >> 4;
    float acc[8][8];
#pragma unroll
    for (int i = 0; i < 8; i++)
#pragma unroll
        for (int j = 0; j < 8; j++) acc[i][j] = 0.f;
    int arow = tid >> 1, acol = (tid & 1) * 4;
    int brow = tid >> 5, bcol = (tid & 31) * 4;
    bool aok = (bm + arow) < M;
    bool bok = (bn + bcol) < Ncols;
    for (int k0 = 0; k0 < K; k0 += BK) {
        float4 av = make_float4(0.f, 0.f, 0.f, 0.f);
        float4 bv = make_float4(0.f, 0.f, 0.f, 0.f);
        if (aok) av = *(const float4*)&A[(size_t)(bm + arow) * lda + k0 + acol];
        if (bok) bv = *(const float4*)&B[(size_t)(k0 + brow) * ldb + bn + bcol];
        As[acol + 0][arow] = av.x; As[acol + 1][arow] = av.y;
        As[acol + 2][arow] = av.z; As[acol + 3][arow] = av.w;
        *(float4*)&Bs[brow][bcol] = bv;
        __syncthreads();
#pragma unroll
        for (int kk = 0; kk < BK; kk++) {
            float a[8], b[8];
            *(float4*)&a[0] = *(const float4*)&As[kk][ty * 8];
            *(float4*)&a[4] = *(const float4*)&As[kk][ty * 8 + 4];
            *(float4*)&b[0] = *(const float4*)&Bs[kk][tx * 8];
            *(float4*)&b[4] = *(const float4*)&Bs[kk][tx * 8 + 4];
#pragma unroll
            for (int i = 0; i < 8; i++)
#pragma unroll
                for (int j = 0; j < 8; j++) acc[i][j] += a[i] * b[j];
        }
        __syncthreads();
    }
#pragma unroll
    for (int i = 0; i < 8; i++) {
        int row = bm + ty * 8 + i;
        if (row >= M) continue;
#pragma unroll
        for (int j = 0; j < 8; j++) {
            int col = bn + tx * 8 + j;
            if (col < Ncols) C[(size_t)row * ldc + col] = acc[i][j];
        }
    }
}

// ---------------- per-node batched GEMM + fused GRU epilogue ----------------
// GATE: z (o<HH) -> writes z*h directly into xc at xcoff; r (o>=HH) -> zr.
// UPDATE: tanh -> h = r*h + (1-r)*hc.
template <int CIN, int OUT, bool GATE>
__global__ void __launch_bounds__(256) node_gemm_kernel(
    const float* __restrict__ xg0, const float* __restrict__ xg1, const float* __restrict__ xg2,
    const float* __restrict__ W, const float* __restrict__ bias,
    float* __restrict__ zr, float* __restrict__ h,
    float* __restrict__ xcdst, int xcoff, int ldxc)
{
    constexpr int KC = 3 * CIN;
    constexpr int F = CIN * BB;
    constexpr int OPT = OUT / 16;
    __shared__ float Xs[8][BB];
    __shared__ float Ws[8][OUT];
    int n = blockIdx.x;
    int tid = threadIdx.x;
    int tx = tid & 15, ty = tid >> 4;
    float acc[OPT][4];
#pragma unroll
    for (int oi = 0; oi < OPT; oi++)
#pragma unroll
        for (int bi = 0; bi < 4; bi++) acc[oi][bi] = 0.f;
    for (int rc = 0; rc < KC; rc += 8) {
#pragma unroll
        for (int e = tid; e < 8 * BB; e += 256) {
            int i = e >> 6, b = e & 63;
            int r = rc + i;
            float v = 0.f;
            if (r < KC) {
                int k = r / CIN;
                int c = r - k * CIN;
                const float* base = (k == 0) ? xg0 : ((k == 1) ? xg1 : xg2);
                v = base[(size_t)n * F + c * BB + b];
            }
            Xs[i][b] = v;
        }
#pragma unroll
        for (int e4 = tid; e4 < 8 * OUT / 4; e4 += 256) {
            int e = e4 * 4;
            int i = e / OUT, o = e % OUT;
            int r = rc + i;
            float4 v = make_float4(0.f, 0.f, 0.f, 0.f);
            if (r < KC) v = *(const float4*)&W[((size_t)n * KC + r) * OUT + o];
            *(float4*)&Ws[i][o] = v;
        }
        __syncthreads();
#pragma unroll
        for (int i = 0; i < 8; i++) {
            float bvals[4];
            *(float4*)&bvals[0] = *(const float4*)&Xs[i][tx * 4];
            float wv[OPT];
#pragma unroll
            for (int q = 0; q < OPT; q += 4)
                *(float4*)&wv[q] = *(const float4*)&Ws[i][ty * OPT + q];
#pragma unroll
            for (int oi = 0; oi < OPT; oi++)
#pragma unroll
                for (int bi = 0; bi < 4; bi++) acc[oi][bi] += wv[oi] * bvals[bi];
        }
        __syncthreads();
    }
#pragma unroll
    for (int oi = 0; oi < OPT; oi++) {
        int o = ty * OPT + oi;
        float bia = bias[(size_t)n * OUT + o];
#pragma unroll
        for (int bi = 0; bi < 4; bi++) {
            int b = tx * 4 + bi;
            float v = acc[oi][bi] + bia;
            if (GATE) {
                float s = 1.f / (1.f + expf(-v));
                if (o < HH) {
                    float hv = h[((size_t)n * HH + o) * BB + b];
                    xcdst[(size_t)n * ldxc + xcoff + o * BB + b] = s * hv;
                } else {
                    zr[((size_t)n * (2 * HH) + o) * BB + b] = s;
                }
            } else {
                float hc = tanhf(v);
                float r = zr[((size_t)n * (2 * HH) + HH + o) * BB + b];
                size_t hi = ((size_t)n * HH + o) * BB + b;
                float hv = h[hi];
                h[hi] = r * hv + (1.f - r) * hc;
            }
        }
    }
}

// ---------------- prep kernels ----------------
__global__ void prep_xc0_kernel(const float* __restrict__ src, int t) {
    long idx = (long)blockIdx.x * blockDim.x + threadIdx.x;
    if (idx >= (long)NN * F0) return;
    int m = (int)(idx / F0);
    int col = (int)(idx - (long)m * F0);
    float v;
    if (col < BB) v = src[((size_t)(col * TT + t)) * NN + m];
    else          v = g_h0[(size_t)m * (HH * BB) + (col - BB)];
    g_xc[idx] = v;
}
__global__ void prep_xc1_kernel() {
    long idx = (long)blockIdx.x * blockDim.x + threadIdx.x;
    if (idx >= (long)NN * F1) return;
    int m = (int)(idx >> 13);
    int e = (int)(idx & 8191);
    float v = (e < HH * BB) ? g_h0[(size_t)m * (HH * BB) + e]
                            : g_h1[(size_t)m * (HH * BB) + (e - HH * BB)];
    g_xc[idx] = v;
}

// ---------------- final projection ----------------
__global__ void __launch_bounds__(256) final_kernel(
    const float* __restrict__ cw, const float* __restrict__ cb, float* __restrict__ out)
{
    __shared__ float hs[HH * BB];
    __shared__ float cws[TT * HH];
    __shared__ float cbs[TT];
    int n = blockIdx.x, tid = threadIdx.x;
    for (int e = tid; e < HH * BB; e += 256) hs[e] = g_h1[(size_t)n * HH * BB + e];
    for (int e = tid; e < TT * HH; e += 256) cws[e] = cw[e];
    if (tid < TT) cbs[tid] = cb[tid];
    __syncthreads();
    for (int p = tid; p < BB * TT; p += 256) {
        int b = p / TT, o = p - b * TT;
        float s = cbs[o];
#pragma unroll
        for (int k = 0; k < HH; k++) s += hs[k * BB + b] * cws[o * HH + k];
        out[((size_t)(b * TT + o)) * NN + n] = s;
    }
}

// ---------------- host ----------------
static void sgemm(const float* A, const float* B, float* C, int M, int Nc, int K,
                  int lda, int ldb, int ldc)
{
    dim3 g((Nc + 127) / 128, (M + 127) / 128);
    sgemm_kernel<<<g, 256>>>(A, B, C, M, Nc, K, lda, ldb, ldc);
}

static void gemm_pair(float* xcp, float* y1p, float* y2p, int c0, int NC, int ld)
{
    dim3 gg((NC + 127) / 128, 32);
    gemm_main_kernel<<<gg, 256, SMEM_MAIN>>>(xcp + c0,
                                             y1p + c0, NN, y2p + c0, 2048, NN,
                                             NC, ld, ld, 1.f);
}

extern "C" void kernel_launch(void* const* d_in, const int* in_sizes, int n_in,
                              void* d_out, int out_size)
{
    const float* src  = (const float*)d_in[0];
    const float* E    = (const float*)d_in[1];
    const float* gwp0 = (const float*)d_in[2];
    const float* gbp0 = (const float*)d_in[3];
    const float* uwp0 = (const float*)d_in[4];
    const float* ubp0 = (const float*)d_in[5];
    const float* gwp1 = (const float*)d_in[6];
    const float* gbp1 = (const float*)d_in[7];
    const float* uwp1 = (const float*)d_in[8];
    const float* ubp1 = (const float*)d_in[9];
    const float* cw   = (const float*)d_in[10];
    const float* cb   = (const float*)d_in[11];
    float* out = (float*)d_out;

    cudaFuncSetAttribute(gemm_main_kernel, cudaFuncAttributeMaxDynamicSharedMemorySize, SMEM_MAIN);

    float *As_, *gW0_, *uW0_, *gW1_, *uW1_, *gb0_, *ub0_, *gb1_, *ub1_;
    float *xc_, *y1_, *y2_, *zr_, *h0_, *h1_;
    cudaGetSymbolAddress((void**)&As_,  g_As);
    cudaGetSymbolAddress((void**)&gW0_, g_gW0);
    cudaGetSymbolAddress((void**)&uW0_, g_uW0);
    cudaGetSymbolAddress((void**)&gW1_, g_gW1);
    cudaGetSymbolAddress((void**)&uW1_, g_uW1);
    cudaGetSymbolAddress((void**)&gb0_, g_gb0);
    cudaGetSymbolAddress((void**)&ub0_, g_ub0);
    cudaGetSymbolAddress((void**)&gb1_, g_gb1);
    cudaGetSymbolAddress((void**)&ub1_, g_ub1);
    cudaGetSymbolAddress((void**)&xc_,  g_xc);
    cudaGetSymbolAddress((void**)&y1_,  g_y1);
    cudaGetSymbolAddress((void**)&y2_,  g_y2);
    cudaGetSymbolAddress((void**)&zr_,  g_zr);
    cudaGetSymbolAddress((void**)&h0_,  g_h0);
    cudaGetSymbolAddress((void**)&h1_,  g_h1);

    cudaMemsetAsync(h0_, 0, (size_t)NN * HH * BB * sizeof(float), 0);
    cudaMemsetAsync(h1_, 0, (size_t)NN * HH * BB * sizeof(float), 0);
    cudaMemsetAsync(As_ + (size_t)2000 * NN, 0, (size_t)48 * NN * sizeof(float), 0);
    // zero pad rows 2000..2047 of xc (B operand reads k<2016)
    cudaMemsetAsync(xc_ + (size_t)2000 * F1, 0, (size_t)48 * F1 * sizeof(float), 0);

    adj_softmax_kernel<<<NN, 256>>>(E);

    // Build AsT for A block, compute 2A^2 - I, then AsT for the squared block.
    {
        dim3 gt(64, 64);
        transposeA_kernel<<<gt, 256>>>(0);
        dim3 gg((NN + 127) / 128, 16);
        gemm_main_kernel<<<gg, 256, SMEM_MAIN>>>(As_,                     // B = A (k-major rows, pad zeroed)
                                                 As_ + (size_t)2048 * NN,
                                                 NN, nullptr, 1 << 30, 0,
                                                 NN, NN, NN, 2.f);
        diag_fix_kernel<<<(NN + 255) / 256, 256>>>();
        transposeA_kernel<<<gt, 256>>>(2048);
    }

    sgemm(E, gwp0, gW0_, NN, KC0 * 2 * HH, DD, DD, KC0 * 2 * HH, KC0 * 2 * HH);
    sgemm(E, uwp0, uW0_, NN, KC0 * HH,     DD, DD, KC0 * HH,     KC0 * HH);
    sgemm(E, gwp1, gW1_, NN, KC1 * 2 * HH, DD, DD, KC1 * 2 * HH, KC1 * 2 * HH);
    sgemm(E, uwp1, uW1_, NN, KC1 * HH,     DD, DD, KC1 * HH,     KC1 * HH);
    sgemm(E, gbp0, gb0_, NN, 2 * HH, DD, DD, 2 * HH, 2 * HH);
    sgemm(E, ubp0, ub0_, NN, HH,     DD, DD, HH,     HH);
    sgemm(E, gbp1, gb1_, NN, 2 * HH, DD, DD, 2 * HH, 2 * HH);
    sgemm(E, ubp1, ub1_, NN, HH,     DD, DD, HH,     HH);

    const int PB = 256;
    for (int t = 0; t < TT; t++) {
        // ===== layer 0 =====
        prep_xc0_kernel<<<(int)(((long)NN * F0 + PB - 1) / PB), PB>>>(src, t);
        gemm_pair(xc_, y1_, y2_, 0, F0, F0);
        node_gemm_kernel<CIN0, 2 * HH, true><<<NN, 256>>>(xc_, y1_, y2_, gW0_, gb0_, zr_, h0_,
                                                          xc_, BB, F0);
        gemm_pair(xc_, y1_, y2_, BB, F0 - BB, F0);
        node_gemm_kernel<CIN0, HH, false><<<NN, 256>>>(xc_, y1_, y2_, uW0_, ub0_, zr_, h0_,
                                                       nullptr, 0, 0);

        // ===== layer 1 =====
        prep_xc1_kernel<<<(int)(((long)NN * F1 + PB - 1) / PB), PB>>>();
        gemm_pair(xc_, y1_, y2_, 0, F1, F1);
        node_gemm_kernel<CIN1, 2 * HH, true><<<NN, 256>>>(xc_, y1_, y2_, gW1_, gb1_, zr_, h1_,
                                                          xc_, HH * BB, F1);
        gemm_pair(xc_, y1_, y2_, HH * BB, F1 - HH * BB, F1);
        node_gemm_kernel<CIN1, HH, false><<<NN, 256>>>(xc_, y1_, y2_, uW1_, ub1_, zr_, h1_,
                                                       nullptr, 0, 0);
    }

    final_kernel<<<NN, 256>>>(cw, cb, out);
}

// round 15
// speedup vs baseline: 4.3918x; 1.0684x over previous
#include <cuda_runtime.h>
#include <math.h>
#include <stdint.h>

typedef unsigned int u32;
typedef unsigned long long u64;

#define NN 2000
#define BB 64
#define TT 12
#define DD 16
#define HH 64

constexpr int CIN0 = 65;
constexpr int CIN1 = 128;
constexpr int F0   = BB * CIN0;   // 4160
constexpr int F1   = BB * CIN1;   // 8192
constexpr int KC0  = 3 * CIN0;    // 195
constexpr int KC1  = 3 * CIN1;    // 384
constexpr int LDA_T = 4096;       // AsT row length (m-padded)
constexpr int KPAD = 2048;        // padded k rows for B operands

// ---------------- device scratch ----------------
// stacked operator rows: 0..1999 = A, 2000..2047 = 0, 2048..4047 = 2A^2 - I
__device__ float g_As[(size_t)4096 * NN];
__device__ float g_AsT[(size_t)2048 * LDA_T];   // AsT[k][m] = As[m][k], zero for k>=2000 / m pad
__device__ float g_gW0[NN * KC0 * 2 * HH];
__device__ float g_uW0[NN * KC0 * HH];
__device__ float g_gW1[NN * KC1 * 2 * HH];
__device__ float g_uW1[NN * KC1 * HH];
__device__ float g_gb0[NN * 2 * HH];
__device__ float g_ub0[NN * HH];
__device__ float g_gb1[NN * 2 * HH];
__device__ float g_ub1[NN * HH];
__device__ float g_xc[(size_t)KPAD * F1];       // B operand: rows 2000..2047 zeroed
__device__ float g_y1[NN * F1];
__device__ float g_y2[NN * F1];
__device__ float g_zr[NN * 2 * HH * BB];
__device__ float g_h0[NN * HH * BB];
__device__ float g_h1[NN * HH * BB];

// ---------------- helpers ----------------
__device__ __forceinline__ u64 pack2(float x, float y) {
    u64 r; asm("mov.b64 %0, {%1,%2};" : "=l"(r) : "f"(x), "f"(y)); return r;
}
__device__ __forceinline__ void unpack2(u64 v, float& x, float& y) {
    asm("mov.b64 {%0,%1}, %2;" : "=f"(x), "=f"(y) : "l"(v));
}
__device__ __forceinline__ void ffma2(u64& d, u64 a, u64 b) {
    asm("fma.rn.f32x2 %0, %1, %2, %0;" : "+l"(d) : "l"(a), "l"(b));
}
__device__ __forceinline__ u32 smem_to_u32(const void* p) {
    u32 a;
    asm("{ .reg .u64 t; cvta.to.shared.u64 t, %1; cvt.u32.u64 %0, t; }" : "=r"(a) : "l"(p));
    return a;
}
#define CP_ASYNC16(d, s) asm volatile("cp.async.cg.shared.global [%0], [%1], 16;" :: "r"((u32)(d)), "l"(s) : "memory")
#define CP_COMMIT()  asm volatile("cp.async.commit_group;" ::: "memory")
#define CP_WAIT1()   asm volatile("cp.async.wait_group 1;" ::: "memory")

// ---------------- adjacency softmax (rows 0..1999 of g_As) ----------------
__global__ void __launch_bounds__(256) adj_softmax_kernel(const float* __restrict__ E) {
    __shared__ float row[NN];
    __shared__ float sred[8];
    int n = blockIdx.x, tid = threadIdx.x;
    int lane = tid & 31, wid = tid >> 5;
    float en[DD];
#pragma unroll
    for (int d = 0; d < DD; d++) en[d] = E[n * DD + d];
    float lmax = 0.f;
    for (int m = tid; m < NN; m += 256) {
        const float* em = &E[m * DD];
        float s = 0.f;
#pragma unroll
        for (int d = 0; d < DD; d++) s += en[d] * em[d];
        s = fmaxf(s, 0.f);
        row[m] = s;
        lmax = fmaxf(lmax, s);
    }
#pragma unroll
    for (int o = 16; o; o >>= 1) lmax = fmaxf(lmax, __shfl_xor_sync(0xffffffffu, lmax, o));
    if (lane == 0) sred[wid] = lmax;
    __syncthreads();
    float bmax = sred[0];
#pragma unroll
    for (int w = 1; w < 8; w++) bmax = fmaxf(bmax, sred[w]);
    float lsum = 0.f;
    for (int m = tid; m < NN; m += 256) {
        float e = expf(row[m] - bmax);
        row[m] = e;
        lsum += e;
    }
#pragma unroll
    for (int o = 16; o; o >>= 1) lsum += __shfl_xor_sync(0xffffffffu, lsum, o);
    __syncthreads();
    if (lane == 0) sred[wid] = lsum;
    __syncthreads();
    float bsum = 0.f;
#pragma unroll
    for (int w = 0; w < 8; w++) bsum += sred[w];
    float inv = 1.f / bsum;
    for (int m = tid; m < NN; m += 256) g_As[(size_t)n * NN + m] = row[m] * inv;
}

__global__ void diag_fix_kernel() {
    int i = blockIdx.x * 256 + threadIdx.x;
    if (i < NN) g_As[(size_t)(2048 + i) * NN + i] -= 1.f;
}

// ---------------- transpose As[m][k] -> AsT[k][m] for m in [mbase, mbase+2048) ----------------
__global__ void __launch_bounds__(256) transposeA_kernel(int mbase) {
    __shared__ float t[32][33];
    int k0 = blockIdx.x * 32, m0 = mbase + blockIdx.y * 32;
    int lx = threadIdx.x & 31, ly = threadIdx.x >> 5;
#pragma unroll
    for (int rr = 0; rr < 4; rr++) {
        int m = m0 + ly + rr * 8, k = k0 + lx;
        float v = 0.f;
        if (m < 4048 && k < NN) v = g_As[(size_t)m * NN + k];
        t[ly + rr * 8][lx] = v;
    }
    __syncthreads();
#pragma unroll
    for (int rr = 0; rr < 4; rr++) {
        int k = k0 + ly + rr * 8;
        int m = m0 + lx;
        g_AsT[(size_t)k * LDA_T + m] = t[lx][ly + rr * 8];
    }
}

// ---------------- main FFMA2 GEMM: C = alpha * As(stacked) @ B ----------------
// A from g_AsT (k-major, zero for k>=2000). B must be valid for k<2016 (pad rows zeroed).
// Output row r: r<m1 -> C1[r]; r>=split && r-split<m2 -> C2[r-split].
// 128x128 C-tile, 256 threads, 8x8 thread tile. Thread columns: {tx*4..+3} U {64+tx*4..+3}
// (conflict-free 16B-stride B loads). BK=32, 3-stage cp.async ring, one barrier per tile.
constexpr int GBK = 32;
constexpr int STAGE_F = GBK * 128 * 2;            // 8192 floats per stage (A + B)
constexpr int SMEM_MAIN = 3 * STAGE_F * 4;        // 96 KB
__global__ void __launch_bounds__(256, 2) gemm_main_kernel(
    const float* __restrict__ B,
    float* __restrict__ C1, int m1,
    float* __restrict__ C2, int split, int m2,
    int Ncols, int ldb, int ldc, float alpha)
{
    extern __shared__ float smemf[];
    u32 sb = smem_to_u32(smemf);
    int tid = threadIdx.x;
    int tx = tid & 15, ty = tid >> 4;
    int bm = blockIdx.y * 128, bn = blockIdx.x * 128;
    const int nk = 63;   // 63 * 32 = 2016 >= 2000

    u64 acc2[8][4];
#pragma unroll
    for (int i = 0; i < 8; i++)
#pragma unroll
        for (int p = 0; p < 4; p++) acc2[i][p] = 0ULL;

    auto stage = [&](int c) {
        if (c < nk) {
            int buf = c % 3;
            const float* At = g_AsT + (size_t)(c * GBK) * LDA_T + bm;
            const float* Bt = B + (size_t)(c * GBK) * ldb + bn;
#pragma unroll
            for (int i = 0; i < 4; i++) {
                int e = tid + i * 256;          // 0..1023
                int k = e >> 5, c4 = e & 31;
                CP_ASYNC16(sb + buf * 32768 + k * 512 + c4 * 16,
                           At + (size_t)k * LDA_T + c4 * 4);
                if (bn + c4 * 4 < Ncols) {
                    CP_ASYNC16(sb + buf * 32768 + 16384 + k * 512 + c4 * 16,
                               Bt + (size_t)k * ldb + c4 * 4);
                } else {
                    *(float4*)(smemf + buf * STAGE_F + GBK * 128 + k * 128 + c4 * 4) =
                        make_float4(0.f, 0.f, 0.f, 0.f);
                }
            }
        }
        CP_COMMIT();
    };

    stage(0); stage(1);

    for (int kt = 0; kt < nk; kt++) {
        int buf = kt % 3;
        CP_WAIT1();
        __syncthreads();
        stage(kt + 2);
#pragma unroll 4
        for (int kk = 0; kk < GBK; kk++) {
            const float* ap = smemf + buf * STAGE_F + kk * 128 + ty * 8;
            float4 a0 = *(const float4*)ap;
            float4 a1 = *(const float4*)(ap + 4);
            const float* bbase = smemf + buf * STAGE_F + GBK * 128 + kk * 128;
            float4 bl = *(const float4*)(bbase + tx * 4);        // cols tx*4..+3
            float4 bh = *(const float4*)(bbase + 64 + tx * 4);   // cols 64+tx*4..+3
            u64 b0 = pack2(bl.x, bl.y), b1 = pack2(bl.z, bl.w);
            u64 b2 = pack2(bh.x, bh.y), b3 = pack2(bh.z, bh.w);
            float a[8] = { a0.x, a0.y, a0.z, a0.w, a1.x, a1.y, a1.z, a1.w };
#pragma unroll
            for (int i = 0; i < 8; i++) {
                u64 ad = pack2(a[i], a[i]);
                ffma2(acc2[i][0], ad, b0);
                ffma2(acc2[i][1], ad, b1);
                ffma2(acc2[i][2], ad, b2);
                ffma2(acc2[i][3], ad, b3);
            }
        }
    }

#pragma unroll
    for (int i = 0; i < 8; i++) {
        int row = bm + ty * 8 + i;
        float* dst;
        if (row < m1) dst = C1 + (size_t)row * ldc;
        else if (row >= split && (row - split) < m2) dst = C2 + (size_t)(row - split) * ldc;
        else continue;
#pragma unroll
        for (int p = 0; p < 4; p++) {
            int cc = bn + ((p < 2) ? (tx * 4 + 2 * p) : (64 + tx * 4 + 2 * (p - 2)));
            if (cc < Ncols) {
                float v0, v1;
                unpack2(acc2[i][p], v0, v1);
                dst[cc]     = alpha * v0;
                dst[cc + 1] = alpha * v1;
            }
        }
    }
}

// ---------------- fp32 GEMM (weight folding only, K=16) ----------------
__global__ void __launch_bounds__(256) sgemm_kernel(
    const float* __restrict__ A, const float* __restrict__ B, float* __restrict__ C,
    int M, int Ncols, int K, int lda, int ldb, int ldc)
{
    constexpr int BM = 128, BN = 128, BK = 8;
    __shared__ float As[BK][BM];
    __shared__ float Bs[BK][BN];
    int tid = threadIdx.x;
    int bm = blockIdx.y * BM, bn = blockIdx.x * BN;
    int tx = tid & 15, ty = tid >> 4;
    float acc[8][8];
#pragma unroll
    for (int i = 0; i < 8; i++)
#pragma unroll
        for (int j = 0; j < 8; j++) acc[i][j] = 0.f;
    int arow = tid >> 1, acol = (tid & 1) * 4;
    int brow = tid >> 5, bcol = (tid & 31) * 4;
    bool aok = (bm + arow) < M;
    bool bok = (bn + bcol) < Ncols;
    for (int k0 = 0; k0 < K; k0 += BK) {
        float4 av = make_float4(0.f, 0.f, 0.f, 0.f);
        float4 bv = make_float4(0.f, 0.f, 0.f, 0.f);
        if (aok) av = *(const float4*)&A[(size_t)(bm + arow) * lda + k0 + acol];
        if (bok) bv = *(const float4*)&B[(size_t)(k0 + brow) * ldb + bn + bcol];
        As[acol + 0][arow] = av.x; As[acol + 1][arow] = av.y;
        As[acol + 2][arow] = av.z; As[acol + 3][arow] = av.w;
        *(float4*)&Bs[brow][bcol] = bv;
        __syncthreads();
#pragma unroll
        for (int kk = 0; kk < BK; kk++) {
            float a[8], b[8];
            *(float4*)&a[0] = *(const float4*)&As[kk][ty * 8];
            *(float4*)&a[4] = *(const float4*)&As[kk][ty * 8 + 4];
            *(float4*)&b[0] = *(const float4*)&Bs[kk][tx * 8];
            *(float4*)&b[4] = *(const float4*)&Bs[kk][tx * 8 + 4];
#pragma unroll
            for (int i = 0; i < 8; i++)
#pragma unroll
                for (int j = 0; j < 8; j++) acc[i][j] += a[i] * b[j];
        }
        __syncthreads();
    }
#pragma unroll
    for (int i = 0; i < 8; i++) {
        int row = bm + ty * 8 + i;
        if (row >= M) continue;
#pragma unroll
        for (int j = 0; j < 8; j++) {
            int col = bn + tx * 8 + j;
            if (col < Ncols) C[(size_t)row * ldc + col] = acc[i][j];
        }
    }
}

// ---------------- per-node batched GEMM + fused GRU epilogue (FFMA2) ----------------
// GATE: z (o<HH) -> writes z*h directly into xc at xcoff; r (o>=HH) -> zr.
// UPDATE: tanh -> h = r*h + (1-r)*hc.
template <int CIN, int OUT, bool GATE>
__global__ void __launch_bounds__(256) node_gemm_kernel(
    const float* __restrict__ xg0, const float* __restrict__ xg1, const float* __restrict__ xg2,
    const float* __restrict__ W, const float* __restrict__ bias,
    float* __restrict__ zr, float* __restrict__ h,
    float* __restrict__ xcdst, int xcoff, int ldxc)
{
    constexpr int KC = 3 * CIN;
    constexpr int F = CIN * BB;
    constexpr int OPT = OUT / 16;   // 8 or 4
    constexpr int OP2 = OPT / 2;    // packed o-pairs
    __shared__ float Xs[8][BB];
    __shared__ float Ws[8][OUT];
    int n = blockIdx.x;
    int tid = threadIdx.x;
    int tx = tid & 15, ty = tid >> 4;

    u64 acc2[OP2][4];
#pragma unroll
    for (int p = 0; p < OP2; p++)
#pragma unroll
        for (int bi = 0; bi < 4; bi++) acc2[p][bi] = 0ULL;

    for (int rc = 0; rc < KC; rc += 8) {
#pragma unroll
        for (int e = tid; e < 8 * BB; e += 256) {
            int i = e >> 6, b = e & 63;
            int r = rc + i;
            float v = 0.f;
            if (r < KC) {
                int k = r / CIN;
                int c = r - k * CIN;
                const float* base = (k == 0) ? xg0 : ((k == 1) ? xg1 : xg2);
                v = base[(size_t)n * F + c * BB + b];
            }
            Xs[i][b] = v;
        }
#pragma unroll
        for (int e4 = tid; e4 < 8 * OUT / 4; e4 += 256) {
            int e = e4 * 4;
            int i = e / OUT, o = e % OUT;
            int r = rc + i;
            float4 v = make_float4(0.f, 0.f, 0.f, 0.f);
            if (r < KC) v = *(const float4*)&W[((size_t)n * KC + r) * OUT + o];
            *(float4*)&Ws[i][o] = v;
        }
        __syncthreads();
#pragma unroll
        for (int i = 0; i < 8; i++) {
            float bvals[4];
            *(float4*)&bvals[0] = *(const float4*)&Xs[i][tx * 4];
            u64 wp[OP2];
            const u64* wsrc = (const u64*)&Ws[i][ty * OPT];
#pragma unroll
            for (int p = 0; p < OP2; p++) wp[p] = wsrc[p];
#pragma unroll
            for (int bi = 0; bi < 4; bi++) {
                u64 bd = pack2(bvals[bi], bvals[bi]);
#pragma unroll
                for (int p = 0; p < OP2; p++) ffma2(acc2[p][bi], wp[p], bd);
            }
        }
        __syncthreads();
    }

#pragma unroll
    for (int p = 0; p < OP2; p++) {
        int o0 = ty * OPT + 2 * p;
        float bia0 = bias[(size_t)n * OUT + o0];
        float bia1 = bias[(size_t)n * OUT + o0 + 1];
#pragma unroll
        for (int bi = 0; bi < 4; bi++) {
            int b = tx * 4 + bi;
            float v0, v1;
            unpack2(acc2[p][bi], v0, v1);
            v0 += bia0; v1 += bia1;
            if (GATE) {
                float s0 = 1.f / (1.f + expf(-v0));
                float s1 = 1.f / (1.f + expf(-v1));
                if (o0 < HH) {
                    float hv0 = h[((size_t)n * HH + o0) * BB + b];
                    float hv1 = h[((size_t)n * HH + o0 + 1) * BB + b];
                    xcdst[(size_t)n * ldxc + xcoff + o0 * BB + b] = s0 * hv0;
                    xcdst[(size_t)n * ldxc + xcoff + (o0 + 1) * BB + b] = s1 * hv1;
                } else {
                    zr[((size_t)n * (2 * HH) + o0) * BB + b] = s0;
                    zr[((size_t)n * (2 * HH) + o0 + 1) * BB + b] = s1;
                }
            } else {
                float hc0 = tanhf(v0);
                float hc1 = tanhf(v1);
                float r0 = zr[((size_t)n * (2 * HH) + HH + o0) * BB + b];
                float r1 = zr[((size_t)n * (2 * HH) + HH + o0 + 1) * BB + b];
                size_t hi0 = ((size_t)n * HH + o0) * BB + b;
                size_t hi1 = ((size_t)n * HH + o0 + 1) * BB + b;
                float hv0 = h[hi0], hv1 = h[hi1];
                h[hi0] = r0 * hv0 + (1.f - r0) * hc0;
                h[hi1] = r1 * hv1 + (1.f - r1) * hc1;
            }
        }
    }
}

// ---------------- prep kernels ----------------
__global__ void prep_xc0_kernel(const float* __restrict__ src, int t) {
    long idx = (long)blockIdx.x * blockDim.x + threadIdx.x;
    if (idx >= (long)NN * F0) return;
    int m = (int)(idx / F0);
    int col = (int)(idx - (long)m * F0);
    float v;
    if (col < BB) v = src[((size_t)(col * TT + t)) * NN + m];
    else          v = g_h0[(size_t)m * (HH * BB) + (col - BB)];
    g_xc[idx] = v;
}
__global__ void prep_xc1_kernel() {
    long idx = (long)blockIdx.x * blockDim.x + threadIdx.x;
    if (idx >= (long)NN * F1) return;
    int m = (int)(idx >> 13);
    int e = (int)(idx & 8191);
    float v = (e < HH * BB) ? g_h0[(size_t)m * (HH * BB) + e]
                            : g_h1[(size_t)m * (HH * BB) + (e - HH * BB)];
    g_xc[idx] = v;
}

// ---------------- final projection ----------------
__global__ void __launch_bounds__(256) final_kernel(
    const float* __restrict__ cw, const float* __restrict__ cb, float* __restrict__ out)
{
    __shared__ float hs[HH * BB];
    __shared__ float cws[TT * HH];
    __shared__ float cbs[TT];
    int n = blockIdx.x, tid = threadIdx.x;
    for (int e = tid; e < HH * BB; e += 256) hs[e] = g_h1[(size_t)n * HH * BB + e];
    for (int e = tid; e < TT * HH; e += 256) cws[e] = cw[e];
    if (tid < TT) cbs[tid] = cb[tid];
    __syncthreads();
    for (int p = tid; p < BB * TT; p += 256) {
        int b = p / TT, o = p - b * TT;
        float s = cbs[o];
#pragma unroll
        for (int k = 0; k < HH; k++) s += hs[k * BB + b] * cws[o * HH + k];
        out[((size_t)(b * TT + o)) * NN + n] = s;
    }
}

// ---------------- host ----------------
static void sgemm(const float* A, const float* B, float* C, int M, int Nc, int K,
                  int lda, int ldb, int ldc)
{
    dim3 g((Nc + 127) / 128, (M + 127) / 128);
    sgemm_kernel<<<g, 256>>>(A, B, C, M, Nc, K, lda, ldb, ldc);
}

static void gemm_pair(float* xcp, float* y1p, float* y2p, int c0, int NC, int ld)
{
    dim3 gg((NC + 127) / 128, 32);
    gemm_main_kernel<<<gg, 256, SMEM_MAIN>>>(xcp + c0,
                                             y1p + c0, NN, y2p + c0, 2048, NN,
                                             NC, ld, ld, 1.f);
}

extern "C" void kernel_launch(void* const* d_in, const int* in_sizes, int n_in,
                              void* d_out, int out_size)
{
    const float* src  = (const float*)d_in[0];
    const float* E    = (const float*)d_in[1];
    const float* gwp0 = (const float*)d_in[2];
    const float* gbp0 = (const float*)d_in[3];
    const float* uwp0 = (const float*)d_in[4];
    const float* ubp0 = (const float*)d_in[5];
    const float* gwp1 = (const float*)d_in[6];
    const float* gbp1 = (const float*)d_in[7];
    const float* uwp1 = (const float*)d_in[8];
    const float* ubp1 = (const float*)d_in[9];
    const float* cw   = (const float*)d_in[10];
    const float* cb   = (const float*)d_in[11];
    float* out = (float*)d_out;

    cudaFuncSetAttribute(gemm_main_kernel, cudaFuncAttributeMaxDynamicSharedMemorySize, SMEM_MAIN);

    float *As_, *gW0_, *uW0_, *gW1_, *uW1_, *gb0_, *ub0_, *gb1_, *ub1_;
    float *xc_, *y1_, *y2_, *zr_, *h0_, *h1_;
    cudaGetSymbolAddress((void**)&As_,  g_As);
    cudaGetSymbolAddress((void**)&gW0_, g_gW0);
    cudaGetSymbolAddress((void**)&uW0_, g_uW0);
    cudaGetSymbolAddress((void**)&gW1_, g_gW1);
    cudaGetSymbolAddress((void**)&uW1_, g_uW1);
    cudaGetSymbolAddress((void**)&gb0_, g_gb0);
    cudaGetSymbolAddress((void**)&ub0_, g_ub0);
    cudaGetSymbolAddress((void**)&gb1_, g_gb1);
    cudaGetSymbolAddress((void**)&ub1_, g_ub1);
    cudaGetSymbolAddress((void**)&xc_,  g_xc);
    cudaGetSymbolAddress((void**)&y1_,  g_y1);
    cudaGetSymbolAddress((void**)&y2_,  g_y2);
    cudaGetSymbolAddress((void**)&zr_,  g_zr);
    cudaGetSymbolAddress((void**)&h0_,  g_h0);
    cudaGetSymbolAddress((void**)&h1_,  g_h1);

    cudaMemsetAsync(h0_, 0, (size_t)NN * HH * BB * sizeof(float), 0);
    cudaMemsetAsync(h1_, 0, (size_t)NN * HH * BB * sizeof(float), 0);
    cudaMemsetAsync(As_ + (size_t)2000 * NN, 0, (size_t)48 * NN * sizeof(float), 0);
    cudaMemsetAsync(xc_ + (size_t)2000 * F1, 0, (size_t)48 * F1 * sizeof(float), 0);

    adj_softmax_kernel<<<NN, 256>>>(E);

    // Build AsT for A block, compute 2A^2 - I, then AsT for the squared block.
    {
        dim3 gt(64, 64);
        transposeA_kernel<<<gt, 256>>>(0);
        dim3 gg((NN + 127) / 128, 16);
        gemm_main_kernel<<<gg, 256, SMEM_MAIN>>>(As_,
                                                 As_ + (size_t)2048 * NN,
                                                 NN, nullptr, 1 << 30, 0,
                                                 NN, NN, NN, 2.f);
        diag_fix_kernel<<<(NN + 255) / 256, 256>>>();
        transposeA_kernel<<<gt, 256>>>(2048);
    }

    sgemm(E, gwp0, gW0_, NN, KC0 * 2 * HH, DD, DD, KC0 * 2 * HH, KC0 * 2 * HH);
    sgemm(E, uwp0, uW0_, NN, KC0 * HH,     DD, DD, KC0 * HH,     KC0 * HH);
    sgemm(E, gwp1, gW1_, NN, KC1 * 2 * HH, DD, DD, KC1 * 2 * HH, KC1 * 2 * HH);
    sgemm(E, uwp1, uW1_, NN, KC1 * HH,     DD, DD, KC1 * HH,     KC1 * HH);
    sgemm(E, gbp0, gb0_, NN, 2 * HH, DD, DD, 2 * HH, 2 * HH);
    sgemm(E, ubp0, ub0_, NN, HH,     DD, DD, HH,     HH);
    sgemm(E, gbp1, gb1_, NN, 2 * HH, DD, DD, 2 * HH, 2 * HH);
    sgemm(E, ubp1, ub1_, NN, HH,     DD, DD, HH,     HH);

    const int PB = 256;
    for (int t = 0; t < TT; t++) {
        // ===== layer 0 =====
        prep_xc0_kernel<<<(int)(((long)NN * F0 + PB - 1) / PB), PB>>>(src, t);
        gemm_pair(xc_, y1_, y2_, 0, F0, F0);
        node_gemm_kernel<CIN0, 2 * HH, true><<<NN, 256>>>(xc_, y1_, y2_, gW0_, gb0_, zr_, h0_,
                                                          xc_, BB, F0);
        gemm_pair(xc_, y1_, y2_, BB, F0 - BB, F0);
        node_gemm_kernel<CIN0, HH, false><<<NN, 256>>>(xc_, y1_, y2_, uW0_, ub0_, zr_, h0_,
                                                       nullptr, 0, 0);

        // ===== layer 1 =====
        prep_xc1_kernel<<<(int)(((long)NN * F1 + PB - 1) / PB), PB>>>();
        gemm_pair(xc_, y1_, y2_, 0, F1, F1);
        node_gemm_kernel<CIN1, 2 * HH, true><<<NN, 256>>>(xc_, y1_, y2_, gW1_, gb1_, zr_, h1_,
                                                          xc_, HH * BB, F1);
        gemm_pair(xc_, y1_, y2_, HH * BB, F1 - HH * BB, F1);
        node_gemm_kernel<CIN1, HH, false><<<NN, 256>>>(xc_, y1_, y2_, uW1_, ub1_, zr_, h1_,
                                                       nullptr, 0, 0);
    }

    final_kernel<<<NN, 256>>>(cw, cb, out);
}

// round 16
// speedup vs baseline: 4.6441x; 1.0574x over previous
#include <cuda_runtime.h>
#include <math.h>
#include <stdint.h>

typedef unsigned int u32;
typedef unsigned long long u64;

#define NN 2000
#define BB 64
#define TT 12
#define DD 16
#define HH 64

constexpr int CIN0 = 65;
constexpr int CIN1 = 128;
constexpr int F0   = BB * CIN0;   // 4160
constexpr int F1   = BB * CIN1;   // 8192
constexpr int KC0  = 3 * CIN0;    // 195
constexpr int KC1  = 3 * CIN1;    // 384
constexpr int LDA_T = 4096;       // AsT row length (m-padded)
constexpr int KPAD = 2048;        // padded k rows for B operands

// ---------------- device scratch ----------------
// stacked operator rows: 0..1999 = A, 2000..2047 = 0, 2048..4047 = 2A^2 - I
__device__ float g_As[(size_t)4096 * NN];
__device__ float g_AsT[(size_t)2048 * LDA_T];   // AsT[k][m] = As[m][k], zero for k>=2000 / m pad
__device__ float g_gW0[NN * KC0 * 2 * HH];
__device__ float g_uW0[NN * KC0 * HH];
__device__ float g_gW1[NN * KC1 * 2 * HH];
__device__ float g_uW1[NN * KC1 * HH];
__device__ float g_gb0[NN * 2 * HH];
__device__ float g_ub0[NN * HH];
__device__ float g_gb1[NN * 2 * HH];
__device__ float g_ub1[NN * HH];
__device__ float g_xc[(size_t)KPAD * F1];       // B operand: rows 2000..2047 zeroed
__device__ float g_y1[NN * F1];
__device__ float g_y2[NN * F1];
__device__ float g_zr[NN * 2 * HH * BB];
__device__ float g_h0[NN * HH * BB];
__device__ float g_h1[NN * HH * BB];

// ---------------- helpers ----------------
__device__ __forceinline__ u64 pack2(float x, float y) {
    u64 r; asm("mov.b64 %0, {%1,%2};" : "=l"(r) : "f"(x), "f"(y)); return r;
}
__device__ __forceinline__ void unpack2(u64 v, float& x, float& y) {
    asm("mov.b64 {%0,%1}, %2;" : "=f"(x), "=f"(y) : "l"(v));
}
__device__ __forceinline__ void ffma2(u64& d, u64 a, u64 b) {
    asm("fma.rn.f32x2 %0, %1, %2, %0;" : "+l"(d) : "l"(a), "l"(b));
}
__device__ __forceinline__ u32 smem_to_u32(const void* p) {
    u32 a;
    asm("{ .reg .u64 t; cvta.to.shared.u64 t, %1; cvt.u32.u64 %0, t; }" : "=r"(a) : "l"(p));
    return a;
}
#define CP_ASYNC16(d, s) asm volatile("cp.async.cg.shared.global [%0], [%1], 16;" :: "r"((u32)(d)), "l"(s) : "memory")
#define CP_COMMIT()  asm volatile("cp.async.commit_group;" ::: "memory")
#define CP_WAIT1()   asm volatile("cp.async.wait_group 1;" ::: "memory")

// ---------------- adjacency softmax (rows 0..1999 of g_As) ----------------
__global__ void __launch_bounds__(256) adj_softmax_kernel(const float* __restrict__ E) {
    __shared__ float row[NN];
    __shared__ float sred[8];
    int n = blockIdx.x, tid = threadIdx.x;
    int lane = tid & 31, wid = tid >> 5;
    float en[DD];
#pragma unroll
    for (int d = 0; d < DD; d++) en[d] = E[n * DD + d];
    float lmax = 0.f;
    for (int m = tid; m < NN; m += 256) {
        const float* em = &E[m * DD];
        float s = 0.f;
#pragma unroll
        for (int d = 0; d < DD; d++) s += en[d] * em[d];
        s = fmaxf(s, 0.f);
        row[m] = s;
        lmax = fmaxf(lmax, s);
    }
#pragma unroll
    for (int o = 16; o; o >>= 1) lmax = fmaxf(lmax, __shfl_xor_sync(0xffffffffu, lmax, o));
    if (lane == 0) sred[wid] = lmax;
    __syncthreads();
    float bmax = sred[0];
#pragma unroll
    for (int w = 1; w < 8; w++) bmax = fmaxf(bmax, sred[w]);
    float lsum = 0.f;
    for (int m = tid; m < NN; m += 256) {
        float e = expf(row[m] - bmax);
        row[m] = e;
        lsum += e;
    }
#pragma unroll
    for (int o = 16; o; o >>= 1) lsum += __shfl_xor_sync(0xffffffffu, lsum, o);
    __syncthreads();
    if (lane == 0) sred[wid] = lsum;
    __syncthreads();
    float bsum = 0.f;
#pragma unroll
    for (int w = 0; w < 8; w++) bsum += sred[w];
    float inv = 1.f / bsum;
    for (int m = tid; m < NN; m += 256) g_As[(size_t)n * NN + m] = row[m] * inv;
}

__global__ void diag_fix_kernel() {
    int i = blockIdx.x * 256 + threadIdx.x;
    if (i < NN) g_As[(size_t)(2048 + i) * NN + i] -= 1.f;
}

// ---------------- transpose As[m][k] -> AsT[k][m] for m in [mbase, mbase+2048) ----------------
__global__ void __launch_bounds__(256) transposeA_kernel(int mbase) {
    __shared__ float t[32][33];
    int k0 = blockIdx.x * 32, m0 = mbase + blockIdx.y * 32;
    int lx = threadIdx.x & 31, ly = threadIdx.x >> 5;
#pragma unroll
    for (int rr = 0; rr < 4; rr++) {
        int m = m0 + ly + rr * 8, k = k0 + lx;
        float v = 0.f;
        if (m < 4048 && k < NN) v = g_As[(size_t)m * NN + k];
        t[ly + rr * 8][lx] = v;
    }
    __syncthreads();
#pragma unroll
    for (int rr = 0; rr < 4; rr++) {
        int k = k0 + ly + rr * 8;
        int m = m0 + lx;
        g_AsT[(size_t)k * LDA_T + m] = t[lx][ly + rr * 8];
    }
}

// ---------------- main FFMA2 GEMM: C = alpha * As(stacked) @ B ----------------
// A from g_AsT (k-major, zero for k>=2000). B must be valid for k<2016 (pad rows zeroed).
// Output row r: r<m1 -> C1[r]; r>=split && r-split<m2 -> C2[r-split].
// 128x128 C-tile, 256 threads, 8x8 thread tile. Thread columns: {tx*4..+3} U {64+tx*4..+3}
// (conflict-free 16B-stride B loads). BK=32, 3-stage cp.async ring, one barrier per tile.
constexpr int GBK = 32;
constexpr int STAGE_F = GBK * 128 * 2;            // 8192 floats per stage (A + B)
constexpr int SMEM_MAIN = 3 * STAGE_F * 4;        // 96 KB
__global__ void __launch_bounds__(256, 2) gemm_main_kernel(
    const float* __restrict__ B,
    float* __restrict__ C1, int m1,
    float* __restrict__ C2, int split, int m2,
    int Ncols, int ldb, int ldc, float alpha)
{
    extern __shared__ float smemf[];
    u32 sb = smem_to_u32(smemf);
    int tid = threadIdx.x;
    int tx = tid & 15, ty = tid >> 4;
    int bm = blockIdx.y * 128, bn = blockIdx.x * 128;
    const int nk = 63;   // 63 * 32 = 2016 >= 2000

    u64 acc2[8][4];
#pragma unroll
    for (int i = 0; i < 8; i++)
#pragma unroll
        for (int p = 0; p < 4; p++) acc2[i][p] = 0ULL;

    auto stage = [&](int c) {
        if (c < nk) {
            int buf = c % 3;
            const float* At = g_AsT + (size_t)(c * GBK) * LDA_T + bm;
            const float* Bt = B + (size_t)(c * GBK) * ldb + bn;
#pragma unroll
            for (int i = 0; i < 4; i++) {
                int e = tid + i * 256;          // 0..1023
                int k = e >> 5, c4 = e & 31;
                CP_ASYNC16(sb + buf * 32768 + k * 512 + c4 * 16,
                           At + (size_t)k * LDA_T + c4 * 4);
                if (bn + c4 * 4 < Ncols) {
                    CP_ASYNC16(sb + buf * 32768 + 16384 + k * 512 + c4 * 16,
                               Bt + (size_t)k * ldb + c4 * 4);
                } else {
                    *(float4*)(smemf + buf * STAGE_F + GBK * 128 + k * 128 + c4 * 4) =
                        make_float4(0.f, 0.f, 0.f, 0.f);
                }
            }
        }
        CP_COMMIT();
    };

    stage(0); stage(1);

    for (int kt = 0; kt < nk; kt++) {
        int buf = kt % 3;
        CP_WAIT1();
        __syncthreads();
        stage(kt + 2);
#pragma unroll 4
        for (int kk = 0; kk < GBK; kk++) {
            const float* ap = smemf + buf * STAGE_F + kk * 128 + ty * 8;
            float4 a0 = *(const float4*)ap;
            float4 a1 = *(const float4*)(ap + 4);
            const float* bbase = smemf + buf * STAGE_F + GBK * 128 + kk * 128;
            float4 bl = *(const float4*)(bbase + tx * 4);        // cols tx*4..+3
            float4 bh = *(const float4*)(bbase + 64 + tx * 4);   // cols 64+tx*4..+3
            u64 b0 = pack2(bl.x, bl.y), b1 = pack2(bl.z, bl.w);
            u64 b2 = pack2(bh.x, bh.y), b3 = pack2(bh.z, bh.w);
            float a[8] = { a0.x, a0.y, a0.z, a0.w, a1.x, a1.y, a1.z, a1.w };
#pragma unroll
            for (int i = 0; i < 8; i++) {
                u64 ad = pack2(a[i], a[i]);
                ffma2(acc2[i][0], ad, b0);
                ffma2(acc2[i][1], ad, b1);
                ffma2(acc2[i][2], ad, b2);
                ffma2(acc2[i][3], ad, b3);
            }
        }
    }

#pragma unroll
    for (int i = 0; i < 8; i++) {
        int row = bm + ty * 8 + i;
        float* dst;
        if (row < m1) dst = C1 + (size_t)row * ldc;
        else if (row >= split && (row - split) < m2) dst = C2 + (size_t)(row - split) * ldc;
        else continue;
#pragma unroll
        for (int p = 0; p < 4; p++) {
            int cc = bn + ((p < 2) ? (tx * 4 + 2 * p) : (64 + tx * 4 + 2 * (p - 2)));
            if (cc < Ncols) {
                float v0, v1;
                unpack2(acc2[i][p], v0, v1);
                // Ncols is always even and cc is even, so cc+1 < Ncols; 8B-aligned.
                *(float2*)&dst[cc] = make_float2(alpha * v0, alpha * v1);
            }
        }
    }
}

// ---------------- fp32 GEMM (weight folding only, K=16) ----------------
__global__ void __launch_bounds__(256) sgemm_kernel(
    const float* __restrict__ A, const float* __restrict__ B, float* __restrict__ C,
    int M, int Ncols, int K, int lda, int ldb, int ldc)
{
    constexpr int BM = 128, BN = 128, BK = 8;
    __shared__ float As[BK][BM];
    __shared__ float Bs[BK][BN];
    int tid = threadIdx.x;
    int bm = blockIdx.y * BM, bn = blockIdx.x * BN;
    int tx = tid & 15, ty = tid >> 4;
    float acc[8][8];
#pragma unroll
    for (int i = 0; i < 8; i++)
#pragma unroll
        for (int j = 0; j < 8; j++) acc[i][j] = 0.f;
    int arow = tid >> 1, acol = (tid & 1) * 4;
    int brow = tid >> 5, bcol = (tid & 31) * 4;
    bool aok = (bm + arow) < M;
    bool bok = (bn + bcol) < Ncols;
    for (int k0 = 0; k0 < K; k0 += BK) {
        float4 av = make_float4(0.f, 0.f, 0.f, 0.f);
        float4 bv = make_float4(0.f, 0.f, 0.f, 0.f);
        if (aok) av = *(const float4*)&A[(size_t)(bm + arow) * lda + k0 + acol];
        if (bok) bv = *(const float4*)&B[(size_t)(k0 + brow) * ldb + bn + bcol];
        As[acol + 0][arow] = av.x; As[acol + 1][arow] = av.y;
        As[acol + 2][arow] = av.z; As[acol + 3][arow] = av.w;
        *(float4*)&Bs[brow][bcol] = bv;
        __syncthreads();
#pragma unroll
        for (int kk = 0; kk < BK; kk++) {
            float a[8], b[8];
            *(float4*)&a[0] = *(const float4*)&As[kk][ty * 8];
            *(float4*)&a[4] = *(const float4*)&As[kk][ty * 8 + 4];
            *(float4*)&b[0] = *(const float4*)&Bs[kk][tx * 8];
            *(float4*)&b[4] = *(const float4*)&Bs[kk][tx * 8 + 4];
#pragma unroll
            for (int i = 0; i < 8; i++)
#pragma unroll
                for (int j = 0; j < 8; j++) acc[i][j] += a[i] * b[j];
        }
        __syncthreads();
    }
#pragma unroll
    for (int i = 0; i < 8; i++) {
        int row = bm + ty * 8 + i;
        if (row >= M) continue;
#pragma unroll
        for (int j = 0; j < 8; j++) {
            int col = bn + tx * 8 + j;
            if (col < Ncols) C[(size_t)row * ldc + col] = acc[i][j];
        }
    }
}

// ---------------- per-node batched GEMM + fused GRU epilogue (FFMA2 + cp.async) ----------------
// GATE: z (o<HH) -> writes z*h directly into xc at xcoff; r (o>=HH) -> zr.
// UPDATE: tanh -> h = r*h + (1-r)*hc.
// 3-stage cp.async ring over 8-row chunks; one barrier per chunk.
template <int CIN, int OUT, bool GATE>
__global__ void __launch_bounds__(256) node_gemm_kernel(
    const float* __restrict__ xg0, const float* __restrict__ xg1, const float* __restrict__ xg2,
    const float* __restrict__ W, const float* __restrict__ bias,
    float* __restrict__ zr, float* __restrict__ h,
    float* __restrict__ xcdst, int xcoff, int ldxc)
{
    constexpr int KC = 3 * CIN;
    constexpr int F = CIN * BB;
    constexpr int OPT = OUT / 16;   // 8 or 4
    constexpr int OP2 = OPT / 2;    // packed o-pairs
    constexpr int NCH = (KC + 7) / 8;     // chunks of 8 rows
    constexpr int XSEG = 128;             // 8*64 floats / 4
    constexpr int WSEG = 2 * OUT;         // 8*OUT floats / 4
    __shared__ float Xs[3][8][BB];
    __shared__ float Ws[3][8][OUT];
    int n = blockIdx.x;
    int tid = threadIdx.x;
    int tx = tid & 15, ty = tid >> 4;
    u32 sXs = smem_to_u32(&Xs[0][0][0]);
    u32 sWs = smem_to_u32(&Ws[0][0][0]);

    u64 acc2[OP2][4];
#pragma unroll
    for (int p = 0; p < OP2; p++)
#pragma unroll
        for (int bi = 0; bi < 4; bi++) acc2[p][bi] = 0ULL;

    auto stage = [&](int c) {
        if (c < NCH) {
            int buf = c - (c / 3) * 3;
            int rc = c * 8;
            for (int e = tid; e < XSEG + WSEG; e += 256) {
                if (e < XSEG) {
                    int i = e >> 4, j = e & 15;
                    int r = rc + i;
                    u32 dst = sXs + (buf * 8 * BB + i * BB + j * 4) * 4;
                    if (r < KC) {
                        int k = r / CIN;
                        int c0 = r - k * CIN;
                        const float* base = (k == 0) ? xg0 : ((k == 1) ? xg1 : xg2);
                        CP_ASYNC16(dst, base + (size_t)n * F + c0 * BB + j * 4);
                    } else {
                        *(float4*)&Xs[buf][i][j * 4] = make_float4(0.f, 0.f, 0.f, 0.f);
                    }
                } else {
                    int w = e - XSEG;
                    int i = w / (OUT / 4), j = w % (OUT / 4);
                    int r = rc + i;
                    u32 dst = sWs + (buf * 8 * OUT + i * OUT + j * 4) * 4;
                    if (r < KC) {
                        CP_ASYNC16(dst, W + ((size_t)n * KC + r) * OUT + j * 4);
                    } else {
                        *(float4*)&Ws[buf][i][j * 4] = make_float4(0.f, 0.f, 0.f, 0.f);
                    }
                }
            }
        }
        CP_COMMIT();
    };

    stage(0); stage(1);

    for (int c = 0; c < NCH; c++) {
        int buf = c - (c / 3) * 3;
        CP_WAIT1();
        __syncthreads();
        stage(c + 2);
#pragma unroll
        for (int i = 0; i < 8; i++) {
            float bvals[4];
            *(float4*)&bvals[0] = *(const float4*)&Xs[buf][i][tx * 4];
            u64 wp[OP2];
            const u64* wsrc = (const u64*)&Ws[buf][i][ty * OPT];
#pragma unroll
            for (int p = 0; p < OP2; p++) wp[p] = wsrc[p];
#pragma unroll
            for (int bi = 0; bi < 4; bi++) {
                u64 bd = pack2(bvals[bi], bvals[bi]);
#pragma unroll
                for (int p = 0; p < OP2; p++) ffma2(acc2[p][bi], wp[p], bd);
            }
        }
    }

#pragma unroll
    for (int p = 0; p < OP2; p++) {
        int o0 = ty * OPT + 2 * p;
        float bia0 = bias[(size_t)n * OUT + o0];
        float bia1 = bias[(size_t)n * OUT + o0 + 1];
#pragma unroll
        for (int bi = 0; bi < 4; bi++) {
            int b = tx * 4 + bi;
            float v0, v1;
            unpack2(acc2[p][bi], v0, v1);
            v0 += bia0; v1 += bia1;
            if (GATE) {
                float s0 = 1.f / (1.f + expf(-v0));
                float s1 = 1.f / (1.f + expf(-v1));
                if (o0 < HH) {
                    float hv0 = h[((size_t)n * HH + o0) * BB + b];
                    float hv1 = h[((size_t)n * HH + o0 + 1) * BB + b];
                    xcdst[(size_t)n * ldxc + xcoff + o0 * BB + b] = s0 * hv0;
                    xcdst[(size_t)n * ldxc + xcoff + (o0 + 1) * BB + b] = s1 * hv1;
                } else {
                    zr[((size_t)n * (2 * HH) + o0) * BB + b] = s0;
                    zr[((size_t)n * (2 * HH) + o0 + 1) * BB + b] = s1;
                }
            } else {
                float hc0 = tanhf(v0);
                float hc1 = tanhf(v1);
                float r0 = zr[((size_t)n * (2 * HH) + HH + o0) * BB + b];
                float r1 = zr[((size_t)n * (2 * HH) + HH + o0 + 1) * BB + b];
                size_t hi0 = ((size_t)n * HH + o0) * BB + b;
                size_t hi1 = ((size_t)n * HH + o0 + 1) * BB + b;
                float hv0 = h[hi0], hv1 = h[hi1];
                h[hi0] = r0 * hv0 + (1.f - r0) * hc0;
                h[hi1] = r1 * hv1 + (1.f - r1) * hc1;
            }
        }
    }
}

// ---------------- prep kernels ----------------
__global__ void prep_xc0_kernel(const float* __restrict__ src, int t) {
    long idx = (long)blockIdx.x * blockDim.x + threadIdx.x;
    if (idx >= (long)NN * F0) return;
    int m = (int)(idx / F0);
    int col = (int)(idx - (long)m * F0);
    float v;
    if (col < BB) v = src[((size_t)(col * TT + t)) * NN + m];
    else          v = g_h0[(size_t)m * (HH * BB) + (col - BB)];
    g_xc[idx] = v;
}
__global__ void prep_xc1_kernel() {
    long idx = (long)blockIdx.x * blockDim.x + threadIdx.x;
    if (idx >= (long)NN * F1) return;
    int m = (int)(idx >> 13);
    int e = (int)(idx & 8191);
    float v = (e < HH * BB) ? g_h0[(size_t)m * (HH * BB) + e]
                            : g_h1[(size_t)m * (HH * BB) + (e - HH * BB)];
    g_xc[idx] = v;
}

// ---------------- final projection ----------------
__global__ void __launch_bounds__(256) final_kernel(
    const float* __restrict__ cw, const float* __restrict__ cb, float* __restrict__ out)
{
    __shared__ float hs[HH * BB];
    __shared__ float cws[TT * HH];
    __shared__ float cbs[TT];
    int n = blockIdx.x, tid = threadIdx.x;
    for (int e = tid; e < HH * BB; e += 256) hs[e] = g_h1[(size_t)n * HH * BB + e];
    for (int e = tid; e < TT * HH; e += 256) cws[e] = cw[e];
    if (tid < TT) cbs[tid] = cb[tid];
    __syncthreads();
    for (int p = tid; p < BB * TT; p += 256) {
        int b = p / TT, o = p - b * TT;
        float s = cbs[o];
#pragma unroll
        for (int k = 0; k < HH; k++) s += hs[k * BB + b] * cws[o * HH + k];
        out[((size_t)(b * TT + o)) * NN + n] = s;
    }
}

// ---------------- host ----------------
static void sgemm(const float* A, const float* B, float* C, int M, int Nc, int K,
                  int lda, int ldb, int ldc)
{
    dim3 g((Nc + 127) / 128, (M + 127) / 128);
    sgemm_kernel<<<g, 256>>>(A, B, C, M, Nc, K, lda, ldb, ldc);
}

static void gemm_pair(float* xcp, float* y1p, float* y2p, int c0, int NC, int ld)
{
    dim3 gg((NC + 127) / 128, 32);
    gemm_main_kernel<<<gg, 256, SMEM_MAIN>>>(xcp + c0,
                                             y1p + c0, NN, y2p + c0, 2048, NN,
                                             NC, ld, ld, 1.f);
}

extern "C" void kernel_launch(void* const* d_in, const int* in_sizes, int n_in,
                              void* d_out, int out_size)
{
    const float* src  = (const float*)d_in[0];
    const float* E    = (const float*)d_in[1];
    const float* gwp0 = (const float*)d_in[2];
    const float* gbp0 = (const float*)d_in[3];
    const float* uwp0 = (const float*)d_in[4];
    const float* ubp0 = (const float*)d_in[5];
    const float* gwp1 = (const float*)d_in[6];
    const float* gbp1 = (const float*)d_in[7];
    const float* uwp1 = (const float*)d_in[8];
    const float* ubp1 = (const float*)d_in[9];
    const float* cw   = (const float*)d_in[10];
    const float* cb   = (const float*)d_in[11];
    float* out = (float*)d_out;

    cudaFuncSetAttribute(gemm_main_kernel, cudaFuncAttributeMaxDynamicSharedMemorySize, SMEM_MAIN);

    float *As_, *gW0_, *uW0_, *gW1_, *uW1_, *gb0_, *ub0_, *gb1_, *ub1_;
    float *xc_, *y1_, *y2_, *zr_, *h0_, *h1_;
    cudaGetSymbolAddress((void**)&As_,  g_As);
    cudaGetSymbolAddress((void**)&gW0_, g_gW0);
    cudaGetSymbolAddress((void**)&uW0_, g_uW0);
    cudaGetSymbolAddress((void**)&gW1_, g_gW1);
    cudaGetSymbolAddress((void**)&uW1_, g_uW1);
    cudaGetSymbolAddress((void**)&gb0_, g_gb0);
    cudaGetSymbolAddress((void**)&ub0_, g_ub0);
    cudaGetSymbolAddress((void**)&gb1_, g_gb1);
    cudaGetSymbolAddress((void**)&ub1_, g_ub1);
    cudaGetSymbolAddress((void**)&xc_,  g_xc);
    cudaGetSymbolAddress((void**)&y1_,  g_y1);
    cudaGetSymbolAddress((void**)&y2_,  g_y2);
    cudaGetSymbolAddress((void**)&zr_,  g_zr);
    cudaGetSymbolAddress((void**)&h0_,  g_h0);
    cudaGetSymbolAddress((void**)&h1_,  g_h1);

    cudaMemsetAsync(h0_, 0, (size_t)NN * HH * BB * sizeof(float), 0);
    cudaMemsetAsync(h1_, 0, (size_t)NN * HH * BB * sizeof(float), 0);
    cudaMemsetAsync(As_ + (size_t)2000 * NN, 0, (size_t)48 * NN * sizeof(float), 0);
    cudaMemsetAsync(xc_ + (size_t)2000 * F1, 0, (size_t)48 * F1 * sizeof(float), 0);

    adj_softmax_kernel<<<NN, 256>>>(E);

    // Build AsT for A block, compute 2A^2 - I, then AsT for the squared block.
    {
        dim3 gt(64, 64);
        transposeA_kernel<<<gt, 256>>>(0);
        dim3 gg((NN + 127) / 128, 16);
        gemm_main_kernel<<<gg, 256, SMEM_MAIN>>>(As_,
                                                 As_ + (size_t)2048 * NN,
                                                 NN, nullptr, 1 << 30, 0,
                                                 NN, NN, NN, 2.f);
        diag_fix_kernel<<<(NN + 255) / 256, 256>>>();
        transposeA_kernel<<<gt, 256>>>(2048);
    }

    sgemm(E, gwp0, gW0_, NN, KC0 * 2 * HH, DD, DD, KC0 * 2 * HH, KC0 * 2 * HH);
    sgemm(E, uwp0, uW0_, NN, KC0 * HH,     DD, DD, KC0 * HH,     KC0 * HH);
    sgemm(E, gwp1, gW1_, NN, KC1 * 2 * HH, DD, DD, KC1 * 2 * HH, KC1 * 2 * HH);
    sgemm(E, uwp1, uW1_, NN, KC1 * HH,     DD, DD, KC1 * HH,     KC1 * HH);
    sgemm(E, gbp0, gb0_, NN, 2 * HH, DD, DD, 2 * HH, 2 * HH);
    sgemm(E, ubp0, ub0_, NN, HH,     DD, DD, HH,     HH);
    sgemm(E, gbp1, gb1_, NN, 2 * HH, DD, DD, 2 * HH, 2 * HH);
    sgemm(E, ubp1, ub1_, NN, HH,     DD, DD, HH,     HH);

    const int PB = 256;
    for (int t = 0; t < TT; t++) {
        // ===== layer 0 =====
        prep_xc0_kernel<<<(int)(((long)NN * F0 + PB - 1) / PB), PB>>>(src, t);
        gemm_pair(xc_, y1_, y2_, 0, F0, F0);
        node_gemm_kernel<CIN0, 2 * HH, true><<<NN, 256>>>(xc_, y1_, y2_, gW0_, gb0_, zr_, h0_,
                                                          xc_, BB, F0);
        gemm_pair(xc_, y1_, y2_, BB, F0 - BB, F0);
        node_gemm_kernel<CIN0, HH, false><<<NN, 256>>>(xc_, y1_, y2_, uW0_, ub0_, zr_, h0_,
                                                       nullptr, 0, 0);

        // ===== layer 1 =====
        prep_xc1_kernel<<<(int)(((long)NN * F1 + PB - 1) / PB), PB>>>();
        gemm_pair(xc_, y1_, y2_, 0, F1, F1);
        node_gemm_kernel<CIN1, 2 * HH, true><<<NN, 256>>>(xc_, y1_, y2_, gW1_, gb1_, zr_, h1_,
                                                          xc_, HH * BB, F1);
        gemm_pair(xc_, y1_, y2_, HH * BB, F1 - HH * BB, F1);
        node_gemm_kernel<CIN1, HH, false><<<NN, 256>>>(xc_, y1_, y2_, uW1_, ub1_, zr_, h1_,
                                                       nullptr, 0, 0);
    }

    final_kernel<<<NN, 256>>>(cw, cb, out);
}

// round 17
// speedup vs baseline: 4.7333x; 1.0192x over previous
#include <cuda_runtime.h>
#include <math.h>
#include <stdint.h>

typedef unsigned int u32;
typedef unsigned long long u64;

#define NN 2000
#define BB 64
#define TT 12
#define DD 16
#define HH 64

constexpr int CIN0 = 65;
constexpr int CIN1 = 128;
constexpr int F0   = BB * CIN0;   // 4160
constexpr int F1   = BB * CIN1;   // 8192
constexpr int KC0  = 3 * CIN0;    // 195
constexpr int KC1  = 3 * CIN1;    // 384
constexpr int LDA_T = 4096;       // AsT row length (m-padded)
constexpr int KPAD = 2048;        // padded k rows for B operands

// ---------------- device scratch ----------------
// stacked operator rows: 0..1999 = A, 2000..2047 = 0, 2048..4047 = 2A^2 - I
__device__ float g_As[(size_t)4096 * NN];
__device__ float g_AsT[(size_t)2048 * LDA_T];   // AsT[k][m] = As[m][k], zero for k>=2000 / m pad
__device__ float g_gW0[NN * KC0 * 2 * HH];
__device__ float g_uW0[NN * KC0 * HH];
__device__ float g_gW1[NN * KC1 * 2 * HH];
__device__ float g_uW1[NN * KC1 * HH];
__device__ float g_gb0[NN * 2 * HH];
__device__ float g_ub0[NN * HH];
__device__ float g_gb1[NN * 2 * HH];
__device__ float g_ub1[NN * HH];
__device__ float g_xc[(size_t)KPAD * F1];       // B operand: rows 2000..2047 zeroed
__device__ float g_y1[NN * F1];
__device__ float g_y2[NN * F1];
__device__ float g_zr[NN * 2 * HH * BB];
__device__ float g_h0[NN * HH * BB];
__device__ float g_h1[NN * HH * BB];

// ---------------- helpers ----------------
__device__ __forceinline__ u64 pack2(float x, float y) {
    u64 r; asm("mov.b64 %0, {%1,%2};" : "=l"(r) : "f"(x), "f"(y)); return r;
}
__device__ __forceinline__ void unpack2(u64 v, float& x, float& y) {
    asm("mov.b64 {%0,%1}, %2;" : "=f"(x), "=f"(y) : "l"(v));
}
__device__ __forceinline__ void ffma2(u64& d, u64 a, u64 b) {
    asm("fma.rn.f32x2 %0, %1, %2, %0;" : "+l"(d) : "l"(a), "l"(b));
}
__device__ __forceinline__ u32 smem_to_u32(const void* p) {
    u32 a;
    asm("{ .reg .u64 t; cvta.to.shared.u64 t, %1; cvt.u32.u64 %0, t; }" : "=r"(a) : "l"(p));
    return a;
}
#define CP_ASYNC16(d, s) asm volatile("cp.async.cg.shared.global [%0], [%1], 16;" :: "r"((u32)(d)), "l"(s) : "memory")
#define CP_COMMIT()  asm volatile("cp.async.commit_group;" ::: "memory")
#define CP_WAIT1()   asm volatile("cp.async.wait_group 1;" ::: "memory")

// ---------------- adjacency softmax (rows 0..1999 of g_As) ----------------
__global__ void __launch_bounds__(256) adj_softmax_kernel(const float* __restrict__ E) {
    __shared__ float row[NN];
    __shared__ float sred[8];
    int n = blockIdx.x, tid = threadIdx.x;
    int lane = tid & 31, wid = tid >> 5;
    float en[DD];
#pragma unroll
    for (int d = 0; d < DD; d++) en[d] = E[n * DD + d];
    float lmax = 0.f;
    for (int m = tid; m < NN; m += 256) {
        const float* em = &E[m * DD];
        float s = 0.f;
#pragma unroll
        for (int d = 0; d < DD; d++) s += en[d] * em[d];
        s = fmaxf(s, 0.f);
        row[m] = s;
        lmax = fmaxf(lmax, s);
    }
#pragma unroll
    for (int o = 16; o; o >>= 1) lmax = fmaxf(lmax, __shfl_xor_sync(0xffffffffu, lmax, o));
    if (lane == 0) sred[wid] = lmax;
    __syncthreads();
    float bmax = sred[0];
#pragma unroll
    for (int w = 1; w < 8; w++) bmax = fmaxf(bmax, sred[w]);
    float lsum = 0.f;
    for (int m = tid; m < NN; m += 256) {
        float e = expf(row[m] - bmax);
        row[m] = e;
        lsum += e;
    }
#pragma unroll
    for (int o = 16; o; o >>= 1) lsum += __shfl_xor_sync(0xffffffffu, lsum, o);
    __syncthreads();
    if (lane == 0) sred[wid] = lsum;
    __syncthreads();
    float bsum = 0.f;
#pragma unroll
    for (int w = 0; w < 8; w++) bsum += sred[w];
    float inv = 1.f / bsum;
    for (int m = tid; m < NN; m += 256) g_As[(size_t)n * NN + m] = row[m] * inv;
}

__global__ void diag_fix_kernel() {
    int i = blockIdx.x * 256 + threadIdx.x;
    if (i < NN) g_As[(size_t)(2048 + i) * NN + i] -= 1.f;
}

// ---------------- transpose As[m][k] -> AsT[k][m] for m in [mbase, mbase+2048) ----------------
__global__ void __launch_bounds__(256) transposeA_kernel(int mbase) {
    __shared__ float t[32][33];
    int k0 = blockIdx.x * 32, m0 = mbase + blockIdx.y * 32;
    int lx = threadIdx.x & 31, ly = threadIdx.x >> 5;
#pragma unroll
    for (int rr = 0; rr < 4; rr++) {
        int m = m0 + ly + rr * 8, k = k0 + lx;
        float v = 0.f;
        if (m < 4048 && k < NN) v = g_As[(size_t)m * NN + k];
        t[ly + rr * 8][lx] = v;
    }
    __syncthreads();
#pragma unroll
    for (int rr = 0; rr < 4; rr++) {
        int k = k0 + ly + rr * 8;
        int m = m0 + lx;
        g_AsT[(size_t)k * LDA_T + m] = t[lx][ly + rr * 8];
    }
}

// ---------------- main FFMA2 GEMM: C = alpha * As(stacked) @ B ----------------
// A from g_AsT (k-major, zero for k>=2000). B must be valid for k<2016 (pad rows zeroed).
// Output row r: r<m1 -> C1[r]; r>=split && r-split<m2 -> C2[r-split].
// 128x128 C-tile, 256 threads, 8x8 thread tile. Row-pair packed accumulators:
// acc2[p][j] = (C[ty*8+2p][colj], C[ty*8+2p+1][colj]); A pairs native from smem,
// B duplicated per column. Thread columns: {tx*4..+3} U {64+tx*4..+3} (conflict-free).
// BK=32, 3-stage cp.async ring, one barrier per tile.
constexpr int GBK = 32;
constexpr int STAGE_F = GBK * 128 * 2;            // 8192 floats per stage (A + B)
constexpr int SMEM_MAIN = 3 * STAGE_F * 4;        // 96 KB
__global__ void __launch_bounds__(256, 2) gemm_main_kernel(
    const float* __restrict__ B,
    float* __restrict__ C1, int m1,
    float* __restrict__ C2, int split, int m2,
    int Ncols, int ldb, int ldc, float alpha)
{
    extern __shared__ float smemf[];
    u32 sb = smem_to_u32(smemf);
    int tid = threadIdx.x;
    int tx = tid & 15, ty = tid >> 4;
    int bm = blockIdx.y * 128, bn = blockIdx.x * 128;
    const int nk = 63;   // 63 * 32 = 2016 >= 2000

    u64 acc2[4][8];
#pragma unroll
    for (int p = 0; p < 4; p++)
#pragma unroll
        for (int j = 0; j < 8; j++) acc2[p][j] = 0ULL;

    auto stage = [&](int c) {
        if (c < nk) {
            int buf = c % 3;
            const float* At = g_AsT + (size_t)(c * GBK) * LDA_T + bm;
            const float* Bt = B + (size_t)(c * GBK) * ldb + bn;
#pragma unroll
            for (int i = 0; i < 4; i++) {
                int e = tid + i * 256;          // 0..1023
                int k = e >> 5, c4 = e & 31;
                CP_ASYNC16(sb + buf * 32768 + k * 512 + c4 * 16,
                           At + (size_t)k * LDA_T + c4 * 4);
                if (bn + c4 * 4 < Ncols) {
                    CP_ASYNC16(sb + buf * 32768 + 16384 + k * 512 + c4 * 16,
                               Bt + (size_t)k * ldb + c4 * 4);
                } else {
                    *(float4*)(smemf + buf * STAGE_F + GBK * 128 + k * 128 + c4 * 4) =
                        make_float4(0.f, 0.f, 0.f, 0.f);
                }
            }
        }
        CP_COMMIT();
    };

    stage(0); stage(1);

    for (int kt = 0; kt < nk; kt++) {
        int buf = kt % 3;
        CP_WAIT1();
        __syncthreads();
        stage(kt + 2);
#pragma unroll 8
        for (int kk = 0; kk < GBK; kk++) {
            const u64* a2p = (const u64*)(smemf + buf * STAGE_F + kk * 128 + ty * 8);
            u64 a0 = a2p[0], a1 = a2p[1], a2v = a2p[2], a3 = a2p[3];
            const float* bbase = smemf + buf * STAGE_F + GBK * 128 + kk * 128;
            float4 bl = *(const float4*)(bbase + tx * 4);        // cols tx*4..+3
            float4 bh = *(const float4*)(bbase + 64 + tx * 4);   // cols 64+tx*4..+3
            float bv[8] = { bl.x, bl.y, bl.z, bl.w, bh.x, bh.y, bh.z, bh.w };
#pragma unroll
            for (int j = 0; j < 8; j++) {
                u64 bd = pack2(bv[j], bv[j]);
                ffma2(acc2[0][j], a0, bd);
                ffma2(acc2[1][j], a1, bd);
                ffma2(acc2[2][j], a2v, bd);
                ffma2(acc2[3][j], a3, bd);
            }
        }
    }

    // epilogue: acc2[p][j] holds rows (bm+ty*8+2p, +1) at column colj.
#pragma unroll
    for (int p = 0; p < 4; p++) {
        int r0 = bm + ty * 8 + 2 * p;
        float* dst0 = nullptr;
        float* dst1 = nullptr;
        if (r0 < m1) dst0 = C1 + (size_t)r0 * ldc;
        else if (r0 >= split && (r0 - split) < m2) dst0 = C2 + (size_t)(r0 - split) * ldc;
        int r1 = r0 + 1;
        if (r1 < m1) dst1 = C1 + (size_t)r1 * ldc;
        else if (r1 >= split && (r1 - split) < m2) dst1 = C2 + (size_t)(r1 - split) * ldc;
        if (!dst0 && !dst1) continue;
#pragma unroll
        for (int j = 0; j < 8; j++) {
            int cc = bn + ((j < 4) ? (tx * 4 + j) : (64 + tx * 4 + (j - 4)));
            if (cc < Ncols) {
                float v0, v1;
                unpack2(acc2[p][j], v0, v1);
                if (dst0) dst0[cc] = alpha * v0;
                if (dst1) dst1[cc] = alpha * v1;
            }
        }
    }
}

// ---------------- fp32 GEMM (weight folding only, K=16) ----------------
__global__ void __launch_bounds__(256) sgemm_kernel(
    const float* __restrict__ A, const float* __restrict__ B, float* __restrict__ C,
    int M, int Ncols, int K, int lda, int ldb, int ldc)
{
    constexpr int BM = 128, BN = 128, BK = 8;
    __shared__ float As[BK][BM];
    __shared__ float Bs[BK][BN];
    int tid = threadIdx.x;
    int bm = blockIdx.y * BM, bn = blockIdx.x * BN;
    int tx = tid & 15, ty = tid >> 4;
    float acc[8][8];
#pragma unroll
    for (int i = 0; i < 8; i++)
#pragma unroll
        for (int j = 0; j < 8; j++) acc[i][j] = 0.f;
    int arow = tid >> 1, acol = (tid & 1) * 4;
    int brow = tid >> 5, bcol = (tid & 31) * 4;
    bool aok = (bm + arow) < M;
    bool bok = (bn + bcol) < Ncols;
    for (int k0 = 0; k0 < K; k0 += BK) {
        float4 av = make_float4(0.f, 0.f, 0.f, 0.f);
        float4 bv = make_float4(0.f, 0.f, 0.f, 0.f);
        if (aok) av = *(const float4*)&A[(size_t)(bm + arow) * lda + k0 + acol];
        if (bok) bv = *(const float4*)&B[(size_t)(k0 + brow) * ldb + bn + bcol];
        As[acol + 0][arow] = av.x; As[acol + 1][arow] = av.y;
        As[acol + 2][arow] = av.z; As[acol + 3][arow] = av.w;
        *(float4*)&Bs[brow][bcol] = bv;
        __syncthreads();
#pragma unroll
        for (int kk = 0; kk < BK; kk++) {
            float a[8], b[8];
            *(float4*)&a[0] = *(const float4*)&As[kk][ty * 8];
            *(float4*)&a[4] = *(const float4*)&As[kk][ty * 8 + 4];
            *(float4*)&b[0] = *(const float4*)&Bs[kk][tx * 8];
            *(float4*)&b[4] = *(const float4*)&Bs[kk][tx * 8 + 4];
#pragma unroll
            for (int i = 0; i < 8; i++)
#pragma unroll
                for (int j = 0; j < 8; j++) acc[i][j] += a[i] * b[j];
        }
        __syncthreads();
    }
#pragma unroll
    for (int i = 0; i < 8; i++) {
        int row = bm + ty * 8 + i;
        if (row >= M) continue;
#pragma unroll
        for (int j = 0; j < 8; j++) {
            int col = bn + tx * 8 + j;
            if (col < Ncols) C[(size_t)row * ldc + col] = acc[i][j];
        }
    }
}

// ---------------- per-node batched GEMM + fused GRU epilogue (FFMA2 + cp.async) ----------------
// GATE: z (o<HH) -> writes z*h directly into xc at xcoff; r (o>=HH) -> zr.
// UPDATE: tanh -> h = r*h + (1-r)*hc.
// 3-stage cp.async ring over 8-row chunks; one barrier per chunk.
template <int CIN, int OUT, bool GATE>
__global__ void __launch_bounds__(256) node_gemm_kernel(
    const float* __restrict__ xg0, const float* __restrict__ xg1, const float* __restrict__ xg2,
    const float* __restrict__ W, const float* __restrict__ bias,
    float* __restrict__ zr, float* __restrict__ h,
    float* __restrict__ xcdst, int xcoff, int ldxc)
{
    constexpr int KC = 3 * CIN;
    constexpr int F = CIN * BB;
    constexpr int OPT = OUT / 16;   // 8 or 4
    constexpr int OP2 = OPT / 2;    // packed o-pairs
    constexpr int NCH = (KC + 7) / 8;     // chunks of 8 rows
    constexpr int XSEG = 128;             // 8*64 floats / 4
    constexpr int WSEG = 2 * OUT;         // 8*OUT floats / 4
    __shared__ float Xs[3][8][BB];
    __shared__ float Ws[3][8][OUT];
    int n = blockIdx.x;
    int tid = threadIdx.x;
    int tx = tid & 15, ty = tid >> 4;
    u32 sXs = smem_to_u32(&Xs[0][0][0]);
    u32 sWs = smem_to_u32(&Ws[0][0][0]);

    u64 acc2[OP2][4];
#pragma unroll
    for (int p = 0; p < OP2; p++)
#pragma unroll
        for (int bi = 0; bi < 4; bi++) acc2[p][bi] = 0ULL;

    auto stage = [&](int c) {
        if (c < NCH) {
            int buf = c - (c / 3) * 3;
            int rc = c * 8;
            for (int e = tid; e < XSEG + WSEG; e += 256) {
                if (e < XSEG) {
                    int i = e >> 4, j = e & 15;
                    int r = rc + i;
                    u32 dst = sXs + (buf * 8 * BB + i * BB + j * 4) * 4;
                    if (r < KC) {
                        int k = r / CIN;
                        int c0 = r - k * CIN;
                        const float* base = (k == 0) ? xg0 : ((k == 1) ? xg1 : xg2);
                        CP_ASYNC16(dst, base + (size_t)n * F + c0 * BB + j * 4);
                    } else {
                        *(float4*)&Xs[buf][i][j * 4] = make_float4(0.f, 0.f, 0.f, 0.f);
                    }
                } else {
                    int w = e - XSEG;
                    int i = w / (OUT / 4), j = w % (OUT / 4);
                    int r = rc + i;
                    u32 dst = sWs + (buf * 8 * OUT + i * OUT + j * 4) * 4;
                    if (r < KC) {
                        CP_ASYNC16(dst, W + ((size_t)n * KC + r) * OUT + j * 4);
                    } else {
                        *(float4*)&Ws[buf][i][j * 4] = make_float4(0.f, 0.f, 0.f, 0.f);
                    }
                }
            }
        }
        CP_COMMIT();
    };

    stage(0); stage(1);

    for (int c = 0; c < NCH; c++) {
        int buf = c - (c / 3) * 3;
        CP_WAIT1();
        __syncthreads();
        stage(c + 2);
#pragma unroll
        for (int i = 0; i < 8; i++) {
            float bvals[4];
            *(float4*)&bvals[0] = *(const float4*)&Xs[buf][i][tx * 4];
            u64 wp[OP2];
            const u64* wsrc = (const u64*)&Ws[buf][i][ty * OPT];
#pragma unroll
            for (int p = 0; p < OP2; p++) wp[p] = wsrc[p];
#pragma unroll
            for (int bi = 0; bi < 4; bi++) {
                u64 bd = pack2(bvals[bi], bvals[bi]);
#pragma unroll
                for (int p = 0; p < OP2; p++) ffma2(acc2[p][bi], wp[p], bd);
            }
        }
    }

#pragma unroll
    for (int p = 0; p < OP2; p++) {
        int o0 = ty * OPT + 2 * p;
        float bia0 = bias[(size_t)n * OUT + o0];
        float bia1 = bias[(size_t)n * OUT + o0 + 1];
#pragma unroll
        for (int bi = 0; bi < 4; bi++) {
            int b = tx * 4 + bi;
            float v0, v1;
            unpack2(acc2[p][bi], v0, v1);
            v0 += bia0; v1 += bia1;
            if (GATE) {
                float s0 = 1.f / (1.f + expf(-v0));
                float s1 = 1.f / (1.f + expf(-v1));
                if (o0 < HH) {
                    float hv0 = h[((size_t)n * HH + o0) * BB + b];
                    float hv1 = h[((size_t)n * HH + o0 + 1) * BB + b];
                    xcdst[(size_t)n * ldxc + xcoff + o0 * BB + b] = s0 * hv0;
                    xcdst[(size_t)n * ldxc + xcoff + (o0 + 1) * BB + b] = s1 * hv1;
                } else {
                    zr[((size_t)n * (2 * HH) + o0) * BB + b] = s0;
                    zr[((size_t)n * (2 * HH) + o0 + 1) * BB + b] = s1;
                }
            } else {
                float hc0 = tanhf(v0);
                float hc1 = tanhf(v1);
                float r0 = zr[((size_t)n * (2 * HH) + HH + o0) * BB + b];
                float r1 = zr[((size_t)n * (2 * HH) + HH + o0 + 1) * BB + b];
                size_t hi0 = ((size_t)n * HH + o0) * BB + b;
                size_t hi1 = ((size_t)n * HH + o0 + 1) * BB + b;
                float hv0 = h[hi0], hv1 = h[hi1];
                h[hi0] = r0 * hv0 + (1.f - r0) * hc0;
                h[hi1] = r1 * hv1 + (1.f - r1) * hc1;
            }
        }
    }
}

// ---------------- prep kernels ----------------
__global__ void prep_xc0_kernel(const float* __restrict__ src, int t) {
    long idx = (long)blockIdx.x * blockDim.x + threadIdx.x;
    if (idx >= (long)NN * F0) return;
    int m = (int)(idx / F0);
    int col = (int)(idx - (long)m * F0);
    float v;
    if (col < BB) v = src[((size_t)(col * TT + t)) * NN + m];
    else          v = g_h0[(size_t)m * (HH * BB) + (col - BB)];
    g_xc[idx] = v;
}
__global__ void prep_xc1_kernel() {
    long idx = (long)blockIdx.x * blockDim.x + threadIdx.x;
    if (idx >= (long)NN * F1) return;
    int m = (int)(idx >> 13);
    int e = (int)(idx & 8191);
    float v = (e < HH * BB) ? g_h0[(size_t)m * (HH * BB) + e]
                            : g_h1[(size_t)m * (HH * BB) + (e - HH * BB)];
    g_xc[idx] = v;
}

// ---------------- final projection ----------------
__global__ void __launch_bounds__(256) final_kernel(
    const float* __restrict__ cw, const float* __restrict__ cb, float* __restrict__ out)
{
    __shared__ float hs[HH * BB];
    __shared__ float cws[TT * HH];
    __shared__ float cbs[TT];
    int n = blockIdx.x, tid = threadIdx.x;
    for (int e = tid; e < HH * BB; e += 256) hs[e] = g_h1[(size_t)n * HH * BB + e];
    for (int e = tid; e < TT * HH; e += 256) cws[e] = cw[e];
    if (tid < TT) cbs[tid] = cb[tid];
    __syncthreads();
    for (int p = tid; p < BB * TT; p += 256) {
        int b = p / TT, o = p - b * TT;
        float s = cbs[o];
#pragma unroll
        for (int k = 0; k < HH; k++) s += hs[k * BB + b] * cws[o * HH + k];
        out[((size_t)(b * TT + o)) * NN + n] = s;
    }
}

// ---------------- host ----------------
static void sgemm(const float* A, const float* B, float* C, int M, int Nc, int K,
                  int lda, int ldb, int ldc)
{
    dim3 g((Nc + 127) / 128, (M + 127) / 128);
    sgemm_kernel<<<g, 256>>>(A, B, C, M, Nc, K, lda, ldb, ldc);
}

static void gemm_pair(float* xcp, float* y1p, float* y2p, int c0, int NC, int ld)
{
    dim3 gg((NC + 127) / 128, 32);
    gemm_main_kernel<<<gg, 256, SMEM_MAIN>>>(xcp + c0,
                                             y1p + c0, NN, y2p + c0, 2048, NN,
                                             NC, ld, ld, 1.f);
}

extern "C" void kernel_launch(void* const* d_in, const int* in_sizes, int n_in,
                              void* d_out, int out_size)
{
    const float* src  = (const float*)d_in[0];
    const float* E    = (const float*)d_in[1];
    const float* gwp0 = (const float*)d_in[2];
    const float* gbp0 = (const float*)d_in[3];
    const float* uwp0 = (const float*)d_in[4];
    const float* ubp0 = (const float*)d_in[5];
    const float* gwp1 = (const float*)d_in[6];
    const float* gbp1 = (const float*)d_in[7];
    const float* uwp1 = (const float*)d_in[8];
    const float* ubp1 = (const float*)d_in[9];
    const float* cw   = (const float*)d_in[10];
    const float* cb   = (const float*)d_in[11];
    float* out = (float*)d_out;

    cudaFuncSetAttribute(gemm_main_kernel, cudaFuncAttributeMaxDynamicSharedMemorySize, SMEM_MAIN);

    float *As_, *gW0_, *uW0_, *gW1_, *uW1_, *gb0_, *ub0_, *gb1_, *ub1_;
    float *xc_, *y1_, *y2_, *zr_, *h0_, *h1_;
    cudaGetSymbolAddress((void**)&As_,  g_As);
    cudaGetSymbolAddress((void**)&gW0_, g_gW0);
    cudaGetSymbolAddress((void**)&uW0_, g_uW0);
    cudaGetSymbolAddress((void**)&gW1_, g_gW1);
    cudaGetSymbolAddress((void**)&uW1_, g_uW1);
    cudaGetSymbolAddress((void**)&gb0_, g_gb0);
    cudaGetSymbolAddress((void**)&ub0_, g_ub0);
    cudaGetSymbolAddress((void**)&gb1_, g_gb1);
    cudaGetSymbolAddress((void**)&ub1_, g_ub1);
    cudaGetSymbolAddress((void**)&xc_,  g_xc);
    cudaGetSymbolAddress((void**)&y1_,  g_y1);
    cudaGetSymbolAddress((void**)&y2_,  g_y2);
    cudaGetSymbolAddress((void**)&zr_,  g_zr);
    cudaGetSymbolAddress((void**)&h0_,  g_h0);
    cudaGetSymbolAddress((void**)&h1_,  g_h1);

    cudaMemsetAsync(h0_, 0, (size_t)NN * HH * BB * sizeof(float), 0);
    cudaMemsetAsync(h1_, 0, (size_t)NN * HH * BB * sizeof(float), 0);
    cudaMemsetAsync(As_ + (size_t)2000 * NN, 0, (size_t)48 * NN * sizeof(float), 0);
    cudaMemsetAsync(xc_ + (size_t)2000 * F1, 0, (size_t)48 * F1 * sizeof(float), 0);

    adj_softmax_kernel<<<NN, 256>>>(E);

    // Build AsT for A block, compute 2A^2 - I, then AsT for the squared block.
    {
        dim3 gt(64, 64);
        transposeA_kernel<<<gt, 256>>>(0);
        dim3 gg((NN + 127) / 128, 16);
        gemm_main_kernel<<<gg, 256, SMEM_MAIN>>>(As_,
                                                 As_ + (size_t)2048 * NN,
                                                 NN, nullptr, 1 << 30, 0,
                                                 NN, NN, NN, 2.f);
        diag_fix_kernel<<<(NN + 255) / 256, 256>>>();
        transposeA_kernel<<<gt, 256>>>(2048);
    }

    sgemm(E, gwp0, gW0_, NN, KC0 * 2 * HH, DD, DD, KC0 * 2 * HH, KC0 * 2 * HH);
    sgemm(E, uwp0, uW0_, NN, KC0 * HH,     DD, DD, KC0 * HH,     KC0 * HH);
    sgemm(E, gwp1, gW1_, NN, KC1 * 2 * HH, DD, DD, KC1 * 2 * HH, KC1 * 2 * HH);
    sgemm(E, uwp1, uW1_, NN, KC1 * HH,     DD, DD, KC1 * HH,     KC1 * HH);
    sgemm(E, gbp0, gb0_, NN, 2 * HH, DD, DD, 2 * HH, 2 * HH);
    sgemm(E, ubp0, ub0_, NN, HH,     DD, DD, HH,     HH);
    sgemm(E, gbp1, gb1_, NN, 2 * HH, DD, DD, 2 * HH, 2 * HH);
    sgemm(E, ubp1, ub1_, NN, HH,     DD, DD, HH,     HH);

    const int PB = 256;
    for (int t = 0; t < TT; t++) {
        // ===== layer 0 =====
        prep_xc0_kernel<<<(int)(((long)NN * F0 + PB - 1) / PB), PB>>>(src, t);
        gemm_pair(xc_, y1_, y2_, 0, F0, F0);
        node_gemm_kernel<CIN0, 2 * HH, true><<<NN, 256>>>(xc_, y1_, y2_, gW0_, gb0_, zr_, h0_,
                                                          xc_, BB, F0);
        gemm_pair(xc_, y1_, y2_, BB, F0 - BB, F0);
        node_gemm_kernel<CIN0, HH, false><<<NN, 256>>>(xc_, y1_, y2_, uW0_, ub0_, zr_, h0_,
                                                       nullptr, 0, 0);

        // ===== layer 1 =====
        prep_xc1_kernel<<<(int)(((long)NN * F1 + PB - 1) / PB), PB>>>();
        gemm_pair(xc_, y1_, y2_, 0, F1, F1);
        node_gemm_kernel<CIN1, 2 * HH, true><<<NN, 256>>>(xc_, y1_, y2_, gW1_, gb1_, zr_, h1_,
                                                          xc_, HH * BB, F1);
        gemm_pair(xc_, y1_, y2_, HH * BB, F1 - HH * BB, F1);
        node_gemm_kernel<CIN1, HH, false><<<NN, 256>>>(xc_, y1_, y2_, uW1_, ub1_, zr_, h1_,
                                                       nullptr, 0, 0);
    }

    final_kernel<<<NN, 256>>>(cw, cb, out);
}